// round 2
// baseline (speedup 1.0000x reference)
#include <cuda_runtime.h>
#include <math.h>

#define BB 2
#define LL 2048
#define DD 512
#define HH 8
#define DK 64
#define SK 40
#define UU 40
#define BH 16            // BB*HH
#define NROWS 32768      // BH*LL
#define NCH 16           // cumsum chunks per (b,h)
#define CH 128           // L per chunk

// ---------------- scratch (device globals; no allocation) ----------------
__device__ float g_q[BB*HH*LL*DK];
__device__ float g_k[BB*HH*LL*DK];
__device__ float g_v[BB*HH*LL*DK];
__device__ float g_scores[BH*UU*LL];
__device__ float g_M[NROWS];
__device__ int   g_Mtop[BH*UU];
__device__ int   g_rank[NROWS];
__device__ float g_mx[BH*UU];
__device__ float g_inv[BH*UU];
__device__ float g_part[BH*NCH*DK];
__device__ float g_offs[BH*NCH*DK];
__device__ float g_updp[8*BH*UU*DK];   // 8 L-split partials (deterministic reduce)
__device__ int   g_idx[LL*SK];

// ---------------- kernel 0: normalize index_sample (int32 vs int64) ----------------
__global__ void k_idx(const unsigned int* __restrict__ raw, int nelem) {
    __shared__ int s_flag;
    if (threadIdx.x == 0) s_flag = 0;
    __syncthreads();
    // If data is int64 (little-endian, values < 2048), every odd 32-bit word is 0.
    int local = 0;
    for (int j = threadIdx.x * 2 + 1; j < nelem; j += blockDim.x * 2)
        if (raw[j] != 0u) local = 1;
    if (local) atomicOr(&s_flag, 1);
    __syncthreads();
    int is32 = s_flag;
    for (int e = threadIdx.x; e < nelem; e += blockDim.x)
        g_idx[e] = is32 ? (int)raw[e] : (int)raw[2 * e];
}

// ---------------- kernel 1: QKV projection GEMM ----------------
// C[m,n] = sum_k x[m,k]*W[i,k] + bias[i];  m in [0,4096), n in [0,1536)
// n -> (w = n>>9, i = n&511, h = i>>6, d = i&63); out layout (B,H,L,dk)
__global__ __launch_bounds__(256) void gemm_qkv(
    const float* __restrict__ x,
    const float* __restrict__ Wq, const float* __restrict__ bq,
    const float* __restrict__ Wk, const float* __restrict__ bk,
    const float* __restrict__ Wv, const float* __restrict__ bv) {
    __shared__ float As[16][128];
    __shared__ float Bs[16][128];
    int tid = threadIdx.x;
    int tx = tid & 15, ty = tid >> 4;
    int m0 = blockIdx.y * 128, n0 = blockIdx.x * 128;
    int w = n0 >> 9;
    const float* W    = (w == 0) ? Wq : (w == 1) ? Wk : Wv;
    const float* bias = (w == 0) ? bq : (w == 1) ? bk : bv;
    float* outp       = (w == 0) ? g_q : (w == 1) ? g_k : g_v;
    int i0 = n0 & 511;

    float acc[8][8];
    #pragma unroll
    for (int i = 0; i < 8; i++)
        #pragma unroll
        for (int j = 0; j < 8; j++) acc[i][j] = 0.f;

    for (int k0 = 0; k0 < 512; k0 += 16) {
        #pragma unroll
        for (int j = 0; j < 2; j++) {
            int f = tid * 2 + j;
            int row = f >> 2, c4 = f & 3;
            float4 a = *(const float4*)(x + (size_t)(m0 + row) * 512 + k0 + c4 * 4);
            As[c4*4+0][row] = a.x; As[c4*4+1][row] = a.y;
            As[c4*4+2][row] = a.z; As[c4*4+3][row] = a.w;
            float4 b = *(const float4*)(W + (size_t)(i0 + row) * 512 + k0 + c4 * 4);
            Bs[c4*4+0][row] = b.x; Bs[c4*4+1][row] = b.y;
            Bs[c4*4+2][row] = b.z; Bs[c4*4+3][row] = b.w;
        }
        __syncthreads();
        #pragma unroll
        for (int kk = 0; kk < 16; kk++) {
            float rA[8], rB[8];
            #pragma unroll
            for (int i = 0; i < 8; i++) rA[i] = As[kk][ty * 8 + i];
            #pragma unroll
            for (int i = 0; i < 8; i++) rB[i] = Bs[kk][tx * 8 + i];
            #pragma unroll
            for (int i = 0; i < 8; i++)
                #pragma unroll
                for (int j = 0; j < 8; j++) acc[i][j] += rA[i] * rB[j];
        }
        __syncthreads();
    }

    #pragma unroll
    for (int i = 0; i < 8; i++) {
        int m = m0 + ty * 8 + i;
        int b_ = m >> 11, l = m & 2047;
        #pragma unroll
        for (int j = 0; j < 8; j++) {
            int ni = i0 + tx * 8 + j;
            int h = ni >> 6, d = ni & 63;
            outp[((((size_t)b_ * HH + h) * LL + l) << 6) + d] = acc[i][j] + bias[ni];
        }
    }
}

// ---------------- kernel 2: sampled scores -> M ----------------
__global__ void k_sampleM() {
    __shared__ float qsh[4][64];
    int w = threadIdx.x >> 5, lane = threadIdx.x & 31;
    int row = blockIdx.x * 4 + w;       // bh*L + l
    int bh = row >> 11, l = row & 2047;
    const float* qrow = g_q + ((size_t)row << 6);
    qsh[w][lane] = qrow[lane];
    qsh[w][lane + 32] = qrow[lane + 32];
    __syncwarp();
    const float4* q4 = (const float4*)qsh[w];

    float d0;
    {
        int idx = g_idx[l * SK + lane];
        const float4* kr = (const float4*)(g_k + ((((size_t)bh << 11) + idx) << 6));
        float s = 0.f;
        #pragma unroll
        for (int i = 0; i < 16; i++) {
            float4 a = q4[i], b = kr[i];
            s += a.x*b.x + a.y*b.y + a.z*b.z + a.w*b.w;
        }
        d0 = s;
    }
    float d1 = -INFINITY, s1 = 0.f;
    if (lane < SK - 32) {
        int idx = g_idx[l * SK + 32 + lane];
        const float4* kr = (const float4*)(g_k + ((((size_t)bh << 11) + idx) << 6));
        float s = 0.f;
        #pragma unroll
        for (int i = 0; i < 16; i++) {
            float4 a = q4[i], b = kr[i];
            s += a.x*b.x + a.y*b.y + a.z*b.z + a.w*b.w;
        }
        d1 = s; s1 = s;
    }
    float mx = fmaxf(d0, d1);
    float sm = d0 + s1;
    #pragma unroll
    for (int o = 16; o; o >>= 1) {
        mx = fmaxf(mx, __shfl_xor_sync(0xffffffffu, mx, o));
        sm += __shfl_xor_sync(0xffffffffu, sm, o);
    }
    if (lane == 0) g_M[row] = mx - sm * (1.0f / LL);
}

// ---------------- kernel 3: top-40 per (b,h) ----------------
__global__ void k_topk() {
    __shared__ float vals[LL];
    __shared__ float rv[256];
    __shared__ int   ri[256];
    int bh = blockIdx.x, t = threadIdx.x;
    for (int j = t; j < LL; j += 256) {
        vals[j] = g_M[bh * LL + j];
        g_rank[bh * LL + j] = -1;
    }
    __syncthreads();
    for (int it = 0; it < UU; it++) {
        float bv = -INFINITY; int bi = LL;
        for (int j = t; j < LL; j += 256) {
            float v = vals[j];
            if (v > bv) { bv = v; bi = j; }   // ascending j => lowest index kept on ties
        }
        rv[t] = bv; ri[t] = bi;
        __syncthreads();
        for (int o = 128; o; o >>= 1) {
            if (t < o) {
                float ov = rv[t + o]; int oi = ri[t + o];
                if (ov > rv[t] || (ov == rv[t] && oi < ri[t])) { rv[t] = ov; ri[t] = oi; }
            }
            __syncthreads();
        }
        if (t == 0) {
            int b0 = ri[0];
            g_Mtop[bh * UU + it] = b0;
            g_rank[bh * LL + b0] = it;
            vals[b0] = -INFINITY;
        }
        __syncthreads();
    }
}

// ---------------- kernel 4: scores = scale * Qtop @ K^T ----------------
#define KT 64
__global__ void k_scores() {
    __shared__ float qtop[UU * DK];
    __shared__ float kt[KT * 65];
    int bh = blockIdx.y, l0 = blockIdx.x * KT, t = threadIdx.x;
    for (int j = t; j < UU * DK; j += 256) {
        int u = j >> 6, d = j & 63;
        int rl = g_Mtop[bh * UU + u];
        qtop[j] = g_q[((((size_t)bh << 11) + rl) << 6) + d];
    }
    for (int j = t; j < KT * DK; j += 256) {
        int li = j >> 6, d = j & 63;
        kt[li * 65 + d] = g_k[((((size_t)bh << 11) + l0 + li) << 6) + d];
    }
    __syncthreads();
    int lsub = t & 63, ug = t >> 6;     // ug 0..3, 10 u-values each
    float accv[10];
    #pragma unroll
    for (int g = 0; g < 10; g++) accv[g] = 0.f;
    for (int d = 0; d < 64; d++) {
        float kv = kt[lsub * 65 + d];
        #pragma unroll
        for (int g = 0; g < 10; g++)
            accv[g] += qtop[(ug + 4 * g) * 64 + d] * kv;
    }
    #pragma unroll
    for (int g = 0; g < 10; g++) {
        int u = ug + 4 * g;
        g_scores[((size_t)(bh * UU + u) << 11) + l0 + lsub] = accv[g] * 0.125f;
    }
}

// ---------------- kernel 5: softmax stats ----------------
__global__ void k_stats() {
    __shared__ float red[256];
    int r = blockIdx.x, t = threadIdx.x;
    const float* s = g_scores + ((size_t)r << 11);
    float mx = -INFINITY;
    for (int j = t; j < LL; j += 256) mx = fmaxf(mx, s[j]);
    red[t] = mx; __syncthreads();
    for (int o = 128; o; o >>= 1) { if (t < o) red[t] = fmaxf(red[t], red[t + o]); __syncthreads(); }
    mx = red[0]; __syncthreads();
    float sm = 0.f;
    for (int j = t; j < LL; j += 256) sm += expf(s[j] - mx);
    red[t] = sm; __syncthreads();
    for (int o = 128; o; o >>= 1) { if (t < o) red[t] += red[t + o]; __syncthreads(); }
    if (t == 0) { g_mx[r] = mx; g_inv[r] = 1.0f / red[0]; }
}

// ---------------- cumsum (context) ----------------
__global__ void k_csum_part() {
    __shared__ float red[256];
    int blk = blockIdx.x;              // bh*NCH + c
    int bh = blk >> 4, c = blk & 15;
    int t = threadIdx.x, d = t & 63, p = t >> 6;
    const float* vb = g_v + ((((size_t)bh << 11) + c * CH) << 6);
    float s = 0.f;
    for (int i = 0; i < 32; i++) s += vb[(p * 32 + i) * 64 + d];
    red[t] = s; __syncthreads();
    if (t < 64)
        g_part[blk * 64 + t] = red[t] + red[t + 64] + red[t + 128] + red[t + 192];
}

__global__ void k_csum_off() {
    int bh = blockIdx.x, d = threadIdx.x;
    float run = 0.f;
    for (int c = 0; c < NCH; c++) {
        g_offs[(bh * NCH + c) * 64 + d] = run;
        run += g_part[(bh * NCH + c) * 64 + d];
    }
}

// context output layout == raw (B,H,L,dk) reshape: offset = ((bh*L + l)*64 + d)
__global__ void k_csum_scan(float* __restrict__ ctx) {
    __shared__ float vsh[CH * 64];
    int blk = blockIdx.x;
    int bh = blk >> 4, c = blk & 15;
    int t = threadIdx.x;
    const float4* vb = (const float4*)(g_v + ((((size_t)bh << 11) + c * CH) << 6));
    float4* vs4 = (float4*)vsh;
    for (int j = t; j < CH * 16; j += 256) vs4[j] = vb[j];
    __syncthreads();
    if (t < 64) {
        float run = g_offs[(bh * NCH + c) * 64 + t];
        for (int i = 0; i < CH; i++) { run += vsh[i * 64 + t]; vsh[i * 64 + t] = run; }
    }
    __syncthreads();
    float4* ob = (float4*)(ctx + ((((size_t)bh << 11) + c * CH) << 6));
    for (int j = t; j < CH * 16; j += 256) ob[j] = vs4[j];
}

// ---------------- kernel 7: upd partials = attn @ V ----------------
__global__ void k_upd() {
    __shared__ float vsh[64 * 64];
    __shared__ float ash[UU * 64];
    __shared__ float smx[UU], sinv[UU];
    int bh = blockIdx.y, ls = blockIdx.x;      // L split 0..7 (256 l each)
    int t = threadIdx.x;
    if (t < UU) { smx[t] = g_mx[bh * UU + t]; sinv[t] = g_inv[bh * UU + t]; }

    int lane2 = (t & 31) * 2, ug = t >> 5;     // u = ug*5 + uu
    float acc[5][2];
    #pragma unroll
    for (int uu = 0; uu < 5; uu++) { acc[uu][0] = 0.f; acc[uu][1] = 0.f; }

    for (int tile = 0; tile < 4; tile++) {
        int l0 = ls * 256 + tile * 64;
        __syncthreads();
        const float4* vb = (const float4*)(g_v + ((((size_t)bh << 11) + l0) << 6));
        float4* vs4 = (float4*)vsh;
        for (int j = t; j < 64 * 16; j += 256) vs4[j] = vb[j];
        for (int j = t; j < UU * 64; j += 256) {
            int u = j >> 6, li = j & 63;
            ash[j] = expf(g_scores[((size_t)(bh * UU + u) << 11) + l0 + li] - smx[u]) * sinv[u];
        }
        __syncthreads();
        for (int li = 0; li < 64; li++) {
            float v0 = vsh[li * 64 + lane2], v1 = vsh[li * 64 + lane2 + 1];
            #pragma unroll
            for (int uu = 0; uu < 5; uu++) {
                float a = ash[(ug * 5 + uu) * 64 + li];
                acc[uu][0] += a * v0;
                acc[uu][1] += a * v1;
            }
        }
    }
    #pragma unroll
    for (int uu = 0; uu < 5; uu++) {
        int r = bh * UU + ug * 5 + uu;
        g_updp[((size_t)ls * BH * UU + r) * 64 + lane2]     = acc[uu][0];
        g_updp[((size_t)ls * BH * UU + r) * 64 + lane2 + 1] = acc[uu][1];
    }
}

// ---------------- kernel 8: reduce upd partials + scatter into context ----------------
__global__ void k_scatter(float* __restrict__ ctx) {
    int r = blockIdx.x, d = threadIdx.x;    // r = bh*UU + u
    int bh = r / UU;
    int l = g_Mtop[r];
    float s = 0.f;
    #pragma unroll
    for (int p = 0; p < 8; p++) s += g_updp[((size_t)p * BH * UU + r) * 64 + d];
    ctx[((((size_t)bh << 11) + l) << 6) + d] = s;
}

// ---------------- kernel 9: attns output ----------------
__global__ void k_attns(float* __restrict__ attns) {
    int row = blockIdx.x;               // bh*L + l  == (b*H+h)*L + l
    int bh = row >> 11;
    int r = g_rank[row];
    float* out = attns + ((size_t)row << 11);
    int t = threadIdx.x;
    if (r < 0) {
        float4 c = make_float4(1.0f / LL, 1.0f / LL, 1.0f / LL, 1.0f / LL);
        float4* o4 = (float4*)out;
        o4[t] = c;
        o4[t + 256] = c;
    } else {
        float mx = g_mx[bh * UU + r], inv = g_inv[bh * UU + r];
        const float* s = g_scores + ((size_t)(bh * UU + r) << 11);
        #pragma unroll
        for (int j = 0; j < 2; j++) {
            int base = (t + j * 256) * 4;
            float4 sv = *(const float4*)(s + base);
            float4 ov;
            ov.x = expf(sv.x - mx) * inv;
            ov.y = expf(sv.y - mx) * inv;
            ov.z = expf(sv.z - mx) * inv;
            ov.w = expf(sv.w - mx) * inv;
            *(float4*)(out + base) = ov;
        }
    }
}

// ---------------- launch ----------------
extern "C" void kernel_launch(void* const* d_in, const int* in_sizes, int n_in,
                              void* d_out, int out_size) {
    const float* x  = (const float*)d_in[0];
    const float* Wq = (const float*)d_in[1];
    const float* bq = (const float*)d_in[2];
    const float* Wk = (const float*)d_in[3];
    const float* bk = (const float*)d_in[4];
    const float* Wv = (const float*)d_in[5];
    const float* bv = (const float*)d_in[6];
    const unsigned int* idxraw = (const unsigned int*)d_in[7];

    float* ctx   = (float*)d_out;
    float* attns = ctx + (size_t)BB * LL * DD;

    k_idx<<<1, 1024>>>(idxraw, LL * SK);
    gemm_qkv<<<dim3(12, 32), 256>>>(x, Wq, bq, Wk, bk, Wv, bv);
    k_sampleM<<<NROWS / 4, 128>>>();
    k_topk<<<BH, 256>>>();
    k_scores<<<dim3(LL / KT, BH), 256>>>();
    k_stats<<<BH * UU, 256>>>();
    k_csum_part<<<BH * NCH, 256>>>();
    k_csum_off<<<BH, 64>>>();
    k_csum_scan<<<BH * NCH, 256>>>(ctx);
    k_upd<<<dim3(8, BH), 256>>>();
    k_scatter<<<BH * UU, 64>>>(ctx);
    k_attns<<<NROWS, 256>>>(attns);
}

// round 3
// speedup vs baseline: 1.0427x; 1.0427x over previous
#include <cuda_runtime.h>
#include <math.h>

#define BB 2
#define LL 2048
#define DD 512
#define HH 8
#define DK 64
#define SK 40
#define UU 40
#define BH 16            // BB*HH
#define NROWS 32768      // BH*LL
#define NCH 16           // cumsum chunks per (b,h)
#define CH 128           // L per chunk

// ---------------- scratch (device globals; no allocation) ----------------
__device__ float g_q[BB*HH*LL*DK];
__device__ float g_k[BB*HH*LL*DK];
__device__ float g_v[BB*HH*LL*DK];
__device__ float g_scores[BH*UU*LL];
__device__ float g_M[NROWS];
__device__ int   g_Mtop[BH*UU];
__device__ int   g_rank[NROWS];
__device__ float g_mx[BH*UU];
__device__ float g_inv[BH*UU];
__device__ float g_part[BH*NCH*DK];
__device__ float g_offs[BH*NCH*DK];
__device__ float g_updp[8*BH*UU*DK];   // 8 L-split partials (deterministic reduce)
__device__ int   g_idx[LL*SK];

// ---------------- kernel 0: normalize index_sample (int32 vs int64) ----------------
__global__ void k_idx(const unsigned int* __restrict__ raw, int nelem) {
    __shared__ int s_flag;
    if (threadIdx.x == 0) s_flag = 0;
    __syncthreads();
    // If data is int64 (little-endian, values < 2048), every odd 32-bit word is 0.
    int local = 0;
    for (int j = threadIdx.x * 2 + 1; j < nelem; j += blockDim.x * 2)
        if (raw[j] != 0u) local = 1;
    if (local) atomicOr(&s_flag, 1);
    __syncthreads();
    int is32 = s_flag;
    for (int e = threadIdx.x; e < nelem; e += blockDim.x)
        g_idx[e] = is32 ? (int)raw[e] : (int)raw[2 * e];
}

// ---------------- kernel 1: QKV projection GEMM (double-buffered) ----------------
// C[m,n] = sum_k x[m,k]*W[i,k] + bias[i];  m in [0,4096), n in [0,1536)
__global__ __launch_bounds__(256) void gemm_qkv(
    const float* __restrict__ x,
    const float* __restrict__ Wq, const float* __restrict__ bq,
    const float* __restrict__ Wk, const float* __restrict__ bk,
    const float* __restrict__ Wv, const float* __restrict__ bv) {
    __shared__ float As[2][16][128];
    __shared__ float Bs[2][16][128];
    int tid = threadIdx.x;
    int tx = tid & 15, ty = tid >> 4;
    int m0 = blockIdx.y * 128, n0 = blockIdx.x * 128;
    int w = n0 >> 9;
    const float* W    = (w == 0) ? Wq : (w == 1) ? Wk : Wv;
    const float* bias = (w == 0) ? bq : (w == 1) ? bk : bv;
    float* outp       = (w == 0) ? g_q : (w == 1) ? g_k : g_v;
    int i0 = n0 & 511;

    int ldrow0 = (tid * 2) >> 2,     ldc0 = ((tid * 2) & 3) * 4;
    int ldrow1 = (tid * 2 + 1) >> 2, ldc1 = ((tid * 2 + 1) & 3) * 4;
    const float* xa0 = x + (size_t)(m0 + ldrow0) * 512 + ldc0;
    const float* xa1 = x + (size_t)(m0 + ldrow1) * 512 + ldc1;
    const float* wb0 = W + (size_t)(i0 + ldrow0) * 512 + ldc0;
    const float* wb1 = W + (size_t)(i0 + ldrow1) * 512 + ldc1;

    float acc[8][8];
    #pragma unroll
    for (int i = 0; i < 8; i++)
        #pragma unroll
        for (int j = 0; j < 8; j++) acc[i][j] = 0.f;

    float4 ra0, ra1, rb0, rb1;
    // preload tile 0
    ra0 = *(const float4*)(xa0); ra1 = *(const float4*)(xa1);
    rb0 = *(const float4*)(wb0); rb1 = *(const float4*)(wb1);
    {
        As[0][ldc0+0][ldrow0]=ra0.x; As[0][ldc0+1][ldrow0]=ra0.y; As[0][ldc0+2][ldrow0]=ra0.z; As[0][ldc0+3][ldrow0]=ra0.w;
        As[0][ldc1+0][ldrow1]=ra1.x; As[0][ldc1+1][ldrow1]=ra1.y; As[0][ldc1+2][ldrow1]=ra1.z; As[0][ldc1+3][ldrow1]=ra1.w;
        Bs[0][ldc0+0][ldrow0]=rb0.x; Bs[0][ldc0+1][ldrow0]=rb0.y; Bs[0][ldc0+2][ldrow0]=rb0.z; Bs[0][ldc0+3][ldrow0]=rb0.w;
        Bs[0][ldc1+0][ldrow1]=rb1.x; Bs[0][ldc1+1][ldrow1]=rb1.y; Bs[0][ldc1+2][ldrow1]=rb1.z; Bs[0][ldc1+3][ldrow1]=rb1.w;
    }
    __syncthreads();

    #pragma unroll 1
    for (int kb = 0; kb < 32; kb++) {
        int cur = kb & 1;
        if (kb < 31) {
            int k0 = (kb + 1) * 16;
            ra0 = *(const float4*)(xa0 + k0); ra1 = *(const float4*)(xa1 + k0);
            rb0 = *(const float4*)(wb0 + k0); rb1 = *(const float4*)(wb1 + k0);
        }
        #pragma unroll
        for (int kk = 0; kk < 16; kk++) {
            const float4* a4 = (const float4*)&As[cur][kk][ty * 8];
            const float4* b4 = (const float4*)&Bs[cur][kk][tx * 8];
            float4 aA = a4[0], aB = a4[1];
            float4 bA = b4[0], bB = b4[1];
            float rA[8] = {aA.x,aA.y,aA.z,aA.w,aB.x,aB.y,aB.z,aB.w};
            float rB[8] = {bA.x,bA.y,bA.z,bA.w,bB.x,bB.y,bB.z,bB.w};
            #pragma unroll
            for (int i = 0; i < 8; i++)
                #pragma unroll
                for (int j = 0; j < 8; j++) acc[i][j] += rA[i] * rB[j];
        }
        if (kb < 31) {
            int nxt = cur ^ 1;
            As[nxt][ldc0+0][ldrow0]=ra0.x; As[nxt][ldc0+1][ldrow0]=ra0.y; As[nxt][ldc0+2][ldrow0]=ra0.z; As[nxt][ldc0+3][ldrow0]=ra0.w;
            As[nxt][ldc1+0][ldrow1]=ra1.x; As[nxt][ldc1+1][ldrow1]=ra1.y; As[nxt][ldc1+2][ldrow1]=ra1.z; As[nxt][ldc1+3][ldrow1]=ra1.w;
            Bs[nxt][ldc0+0][ldrow0]=rb0.x; Bs[nxt][ldc0+1][ldrow0]=rb0.y; Bs[nxt][ldc0+2][ldrow0]=rb0.z; Bs[nxt][ldc0+3][ldrow0]=rb0.w;
            Bs[nxt][ldc1+0][ldrow1]=rb1.x; Bs[nxt][ldc1+1][ldrow1]=rb1.y; Bs[nxt][ldc1+2][ldrow1]=rb1.z; Bs[nxt][ldc1+3][ldrow1]=rb1.w;
            __syncthreads();
        }
    }

    #pragma unroll
    for (int i = 0; i < 8; i++) {
        int m = m0 + ty * 8 + i;
        int b_ = m >> 11, l = m & 2047;
        #pragma unroll
        for (int j = 0; j < 8; j++) {
            int ni = i0 + tx * 8 + j;
            int h = ni >> 6, d = ni & 63;
            outp[((((size_t)b_ * HH + h) * LL + l) << 6) + d] = acc[i][j] + bias[ni];
        }
    }
}

// ---------------- kernel 2: sampled scores -> M ----------------
__global__ void k_sampleM() {
    __shared__ float qsh[4][64];
    int w = threadIdx.x >> 5, lane = threadIdx.x & 31;
    int row = blockIdx.x * 4 + w;       // bh*L + l
    int bh = row >> 11, l = row & 2047;
    const float* qrow = g_q + ((size_t)row << 6);
    qsh[w][lane] = qrow[lane];
    qsh[w][lane + 32] = qrow[lane + 32];
    __syncwarp();
    const float4* q4 = (const float4*)qsh[w];

    float d0;
    {
        int idx = g_idx[l * SK + lane];
        const float4* kr = (const float4*)(g_k + ((((size_t)bh << 11) + idx) << 6));
        float s = 0.f;
        #pragma unroll
        for (int i = 0; i < 16; i++) {
            float4 a = q4[i], b = kr[i];
            s += a.x*b.x + a.y*b.y + a.z*b.z + a.w*b.w;
        }
        d0 = s;
    }
    float d1 = -INFINITY, s1 = 0.f;
    if (lane < SK - 32) {
        int idx = g_idx[l * SK + 32 + lane];
        const float4* kr = (const float4*)(g_k + ((((size_t)bh << 11) + idx) << 6));
        float s = 0.f;
        #pragma unroll
        for (int i = 0; i < 16; i++) {
            float4 a = q4[i], b = kr[i];
            s += a.x*b.x + a.y*b.y + a.z*b.z + a.w*b.w;
        }
        d1 = s; s1 = s;
    }
    float mx = fmaxf(d0, d1);
    float sm = d0 + s1;
    #pragma unroll
    for (int o = 16; o; o >>= 1) {
        mx = fmaxf(mx, __shfl_xor_sync(0xffffffffu, mx, o));
        sm += __shfl_xor_sync(0xffffffffu, sm, o);
    }
    if (lane == 0) g_M[row] = mx - sm * (1.0f / LL);
}

// ---------------- kernel 3: exact top-40 per (b,h) via radix select ----------------
// Downstream outputs are invariant to the slot-order of the selected set, so only
// the SET must match jax.lax.top_k (ties: lowest index wins).
__global__ void k_topk() {
    __shared__ unsigned int uvals[LL];     // 8KB
    __shared__ int hist[256];
    __shared__ unsigned int s_prefix;
    __shared__ int s_want, s_slot;
    int bh = blockIdx.x, t = threadIdx.x;
    for (int j = t; j < LL; j += 256) {
        unsigned int b = __float_as_uint(g_M[bh * LL + j]);
        uvals[j] = (b & 0x80000000u) ? ~b : (b | 0x80000000u);
        g_rank[bh * LL + j] = -1;
    }
    if (t == 0) { s_want = UU; s_prefix = 0u; s_slot = 0; }
    __syncthreads();

    #pragma unroll
    for (int level = 0; level < 4; level++) {
        int shift = 24 - level * 8;
        unsigned int mask = (level == 0) ? 0u : (0xFFFFFFFFu << (32 - 8 * level));
        if (t < 256) hist[t] = 0;
        __syncthreads();
        unsigned int pref = s_prefix;
        for (int j = t; j < LL; j += 256) {
            unsigned int u = uvals[j];
            if ((u & mask) == pref)
                atomicAdd(&hist[(u >> shift) & 0xFF], 1);
        }
        __syncthreads();
        if (t == 0) {
            int want = s_want, acc = 0, b = 255;
            for (; b > 0; b--) {
                if (acc + hist[b] >= want) break;
                acc += hist[b];
            }
            s_want = want - acc;
            s_prefix = pref | ((unsigned int)b << shift);
        }
        __syncthreads();
    }

    unsigned int T = s_prefix;   // exact bit pattern of 40th-largest value
    int r = s_want;              // how many ==T elements to take (lowest index first)
    for (int j = t; j < LL; j += 256) {
        unsigned int u = uvals[j];
        bool sel = false;
        if (u > T) sel = true;
        else if (u == T) {
            int rank_eq = 0;
            for (int j2 = 0; j2 < j; j2++) if (uvals[j2] == T) rank_eq++;
            sel = (rank_eq < r);
        }
        if (sel) {
            int slot = atomicAdd(&s_slot, 1);
            g_Mtop[bh * UU + slot] = j;
            g_rank[bh * LL + j] = slot;
        }
    }
}

// ---------------- kernel 4: scores = scale * Qtop @ K^T ----------------
#define KT 64
__global__ void k_scores() {
    __shared__ float qtop[UU * DK];
    __shared__ float kt[KT * 65];
    int bh = blockIdx.y, l0 = blockIdx.x * KT, t = threadIdx.x;
    for (int j = t; j < UU * DK; j += 256) {
        int u = j >> 6, d = j & 63;
        int rl = g_Mtop[bh * UU + u];
        qtop[j] = g_q[((((size_t)bh << 11) + rl) << 6) + d];
    }
    for (int j = t; j < KT * DK; j += 256) {
        int li = j >> 6, d = j & 63;
        kt[li * 65 + d] = g_k[((((size_t)bh << 11) + l0 + li) << 6) + d];
    }
    __syncthreads();
    int lsub = t & 63, ug = t >> 6;     // ug 0..3, 10 u-values each
    float accv[10];
    #pragma unroll
    for (int g = 0; g < 10; g++) accv[g] = 0.f;
    for (int d = 0; d < 64; d++) {
        float kv = kt[lsub * 65 + d];
        #pragma unroll
        for (int g = 0; g < 10; g++)
            accv[g] += qtop[(ug + 4 * g) * 64 + d] * kv;
    }
    #pragma unroll
    for (int g = 0; g < 10; g++) {
        int u = ug + 4 * g;
        g_scores[((size_t)(bh * UU + u) << 11) + l0 + lsub] = accv[g] * 0.125f;
    }
}

// ---------------- kernel 5: softmax stats ----------------
__global__ void k_stats() {
    __shared__ float red[256];
    int r = blockIdx.x, t = threadIdx.x;
    const float* s = g_scores + ((size_t)r << 11);
    float mx = -INFINITY;
    for (int j = t; j < LL; j += 256) mx = fmaxf(mx, s[j]);
    red[t] = mx; __syncthreads();
    for (int o = 128; o; o >>= 1) { if (t < o) red[t] = fmaxf(red[t], red[t + o]); __syncthreads(); }
    mx = red[0]; __syncthreads();
    float sm = 0.f;
    for (int j = t; j < LL; j += 256) sm += expf(s[j] - mx);
    red[t] = sm; __syncthreads();
    for (int o = 128; o; o >>= 1) { if (t < o) red[t] += red[t + o]; __syncthreads(); }
    if (t == 0) { g_mx[r] = mx; g_inv[r] = 1.0f / red[0]; }
}

// ---------------- cumsum (context) ----------------
__global__ void k_csum_part() {
    __shared__ float red[256];
    int blk = blockIdx.x;              // bh*NCH + c
    int bh = blk >> 4, c = blk & 15;
    int t = threadIdx.x, d = t & 63, p = t >> 6;
    const float* vb = g_v + ((((size_t)bh << 11) + c * CH) << 6);
    float s = 0.f;
    for (int i = 0; i < 32; i++) s += vb[(p * 32 + i) * 64 + d];
    red[t] = s; __syncthreads();
    if (t < 64)
        g_part[blk * 64 + t] = red[t] + red[t + 64] + red[t + 128] + red[t + 192];
}

__global__ void k_csum_off() {
    int bh = blockIdx.x, d = threadIdx.x;
    float run = 0.f;
    for (int c = 0; c < NCH; c++) {
        g_offs[(bh * NCH + c) * 64 + d] = run;
        run += g_part[(bh * NCH + c) * 64 + d];
    }
}

// context output layout == raw (B,H,L,dk) reshape: offset = ((bh*L + l)*64 + d)
__global__ void k_csum_scan(float* __restrict__ ctx) {
    __shared__ float vsh[CH * 64];
    int blk = blockIdx.x;
    int bh = blk >> 4, c = blk & 15;
    int t = threadIdx.x;
    const float4* vb = (const float4*)(g_v + ((((size_t)bh << 11) + c * CH) << 6));
    float4* vs4 = (float4*)vsh;
    for (int j = t; j < CH * 16; j += 256) vs4[j] = vb[j];
    __syncthreads();
    if (t < 64) {
        float run = g_offs[(bh * NCH + c) * 64 + t];
        for (int i = 0; i < CH; i++) { run += vsh[i * 64 + t]; vsh[i * 64 + t] = run; }
    }
    __syncthreads();
    float4* ob = (float4*)(ctx + ((((size_t)bh << 11) + c * CH) << 6));
    for (int j = t; j < CH * 16; j += 256) ob[j] = vs4[j];
}

// ---------------- kernel 7: upd partials = attn @ V ----------------
__global__ void k_upd() {
    __shared__ float vsh[64 * 64];
    __shared__ float ash[UU * 64];
    __shared__ float smx[UU], sinv[UU];
    int bh = blockIdx.y, ls = blockIdx.x;      // L split 0..7 (256 l each)
    int t = threadIdx.x;
    if (t < UU) { smx[t] = g_mx[bh * UU + t]; sinv[t] = g_inv[bh * UU + t]; }

    int lane2 = (t & 31) * 2, ug = t >> 5;     // u = ug*5 + uu
    float acc[5][2];
    #pragma unroll
    for (int uu = 0; uu < 5; uu++) { acc[uu][0] = 0.f; acc[uu][1] = 0.f; }

    for (int tile = 0; tile < 4; tile++) {
        int l0 = ls * 256 + tile * 64;
        __syncthreads();
        const float4* vb = (const float4*)(g_v + ((((size_t)bh << 11) + l0) << 6));
        float4* vs4 = (float4*)vsh;
        for (int j = t; j < 64 * 16; j += 256) vs4[j] = vb[j];
        for (int j = t; j < UU * 64; j += 256) {
            int u = j >> 6, li = j & 63;
            ash[j] = expf(g_scores[((size_t)(bh * UU + u) << 11) + l0 + li] - smx[u]) * sinv[u];
        }
        __syncthreads();
        for (int li = 0; li < 64; li++) {
            float v0 = vsh[li * 64 + lane2], v1 = vsh[li * 64 + lane2 + 1];
            #pragma unroll
            for (int uu = 0; uu < 5; uu++) {
                float a = ash[(ug * 5 + uu) * 64 + li];
                acc[uu][0] += a * v0;
                acc[uu][1] += a * v1;
            }
        }
    }
    #pragma unroll
    for (int uu = 0; uu < 5; uu++) {
        int r = bh * UU + ug * 5 + uu;
        g_updp[((size_t)ls * BH * UU + r) * 64 + lane2]     = acc[uu][0];
        g_updp[((size_t)ls * BH * UU + r) * 64 + lane2 + 1] = acc[uu][1];
    }
}

// ---------------- kernel 8: reduce upd partials + scatter into context ----------------
__global__ void k_scatter(float* __restrict__ ctx) {
    int r = blockIdx.x, d = threadIdx.x;    // r = bh*UU + u
    int bh = r / UU;
    int l = g_Mtop[r];
    float s = 0.f;
    #pragma unroll
    for (int p = 0; p < 8; p++) s += g_updp[((size_t)p * BH * UU + r) * 64 + d];
    ctx[((((size_t)bh << 11) + l) << 6) + d] = s;
}

// ---------------- kernel 9: attns output ----------------
__global__ void k_attns(float* __restrict__ attns) {
    int row = blockIdx.x;               // bh*L + l  == (b*H+h)*L + l
    int bh = row >> 11;
    int r = g_rank[row];
    float* out = attns + ((size_t)row << 11);
    int t = threadIdx.x;
    if (r < 0) {
        float4 c = make_float4(1.0f / LL, 1.0f / LL, 1.0f / LL, 1.0f / LL);
        float4* o4 = (float4*)out;
        o4[t] = c;
        o4[t + 256] = c;
    } else {
        float mx = g_mx[bh * UU + r], inv = g_inv[bh * UU + r];
        const float* s = g_scores + ((size_t)(bh * UU + r) << 11);
        #pragma unroll
        for (int j = 0; j < 2; j++) {
            int base = (t + j * 256) * 4;
            float4 sv = *(const float4*)(s + base);
            float4 ov;
            ov.x = expf(sv.x - mx) * inv;
            ov.y = expf(sv.y - mx) * inv;
            ov.z = expf(sv.z - mx) * inv;
            ov.w = expf(sv.w - mx) * inv;
            *(float4*)(out + base) = ov;
        }
    }
}

// ---------------- launch ----------------
extern "C" void kernel_launch(void* const* d_in, const int* in_sizes, int n_in,
                              void* d_out, int out_size) {
    const float* x  = (const float*)d_in[0];
    const float* Wq = (const float*)d_in[1];
    const float* bq = (const float*)d_in[2];
    const float* Wk = (const float*)d_in[3];
    const float* bk = (const float*)d_in[4];
    const float* Wv = (const float*)d_in[5];
    const float* bv = (const float*)d_in[6];
    const unsigned int* idxraw = (const unsigned int*)d_in[7];

    float* ctx   = (float*)d_out;
    float* attns = ctx + (size_t)BB * LL * DD;

    k_idx<<<1, 1024>>>(idxraw, LL * SK);
    gemm_qkv<<<dim3(12, 32), 256>>>(x, Wq, bq, Wk, bk, Wv, bv);
    k_sampleM<<<NROWS / 4, 128>>>();
    k_topk<<<BH, 256>>>();
    k_scores<<<dim3(LL / KT, BH), 256>>>();
    k_stats<<<BH * UU, 256>>>();
    k_csum_part<<<BH * NCH, 256>>>();
    k_csum_off<<<BH, 64>>>();
    k_csum_scan<<<BH * NCH, 256>>>(ctx);
    k_upd<<<dim3(8, BH), 256>>>();
    k_scatter<<<BH * UU, 64>>>(ctx);
    k_attns<<<NROWS, 256>>>(attns);
}

// round 5
// speedup vs baseline: 1.3289x; 1.2745x over previous
#include <cuda_runtime.h>
#include <cuda_fp16.h>
#include <math.h>

#define BB 2
#define LL 2048
#define DD 512
#define HH 8
#define DK 64
#define SK 40
#define UU 40
#define BH 16            // BB*HH
#define NROWS 32768      // BH*LL
#define NCH 16           // cumsum chunks per (b,h)
#define CH 128           // L per chunk

// ---------------- scratch (device globals; no allocation) ----------------
__device__ float g_q[BB*HH*LL*DK];
__device__ float g_k[BB*HH*LL*DK];
__device__ float g_v[BB*HH*LL*DK];
__device__ float g_scores[BH*UU*LL];
__device__ float g_M[NROWS];
__device__ int   g_Mtop[BH*UU];
__device__ int   g_rank[NROWS];
__device__ float g_mx[BH*UU];
__device__ float g_inv[BH*UU];
__device__ float g_part[BH*NCH*DK];
__device__ float g_offs[BH*NCH*DK];
__device__ float g_updp[8*BH*UU*DK];
__device__ int   g_idx[LL*SK];
// fp16x3 split operands (16B-aligned for float4 access)
__device__ __align__(16) __half g_xh[BB*LL*DD];
__device__ __align__(16) __half g_xl[BB*LL*DD];
__device__ __align__(16) __half g_wh[3*DD*DD];
__device__ __align__(16) __half g_wl[3*DD*DD];

// ---------------- kernel 0: normalize index_sample (int32 vs int64) ----------------
__global__ void k_idx(const unsigned int* __restrict__ raw, int nelem) {
    __shared__ int s_flag;
    if (threadIdx.x == 0) s_flag = 0;
    __syncthreads();
    int local = 0;
    for (int j = threadIdx.x * 2 + 1; j < nelem; j += blockDim.x * 2)
        if (raw[j] != 0u) local = 1;
    if (local) atomicOr(&s_flag, 1);
    __syncthreads();
    int is32 = s_flag;
    for (int e = threadIdx.x; e < nelem; e += blockDim.x)
        g_idx[e] = is32 ? (int)raw[e] : (int)raw[2 * e];
}

// ---------------- fp16 hi/lo split converters ----------------
__global__ void k_cvt_x(const float* __restrict__ x) {
    int i4 = blockIdx.x * blockDim.x + threadIdx.x;     // 4 elems each
    if (i4 >= BB*LL*DD/4) return;
    float4 v = ((const float4*)x)[i4];
    __half h0 = __float2half(v.x), h1 = __float2half(v.y);
    __half h2 = __float2half(v.z), h3 = __float2half(v.w);
    __half l0 = __float2half(v.x - __half2float(h0));
    __half l1 = __float2half(v.y - __half2float(h1));
    __half l2 = __float2half(v.z - __half2float(h2));
    __half l3 = __float2half(v.w - __half2float(h3));
    ((__half2*)g_xh)[i4*2]   = __halves2half2(h0, h1);
    ((__half2*)g_xh)[i4*2+1] = __halves2half2(h2, h3);
    ((__half2*)g_xl)[i4*2]   = __halves2half2(l0, l1);
    ((__half2*)g_xl)[i4*2+1] = __halves2half2(l2, l3);
}

__global__ void k_cvt_w(const float* __restrict__ Wq, const float* __restrict__ Wk,
                        const float* __restrict__ Wv) {
    int i4 = blockIdx.x * blockDim.x + threadIdx.x;
    int per = DD*DD/4;
    if (i4 >= 3*per) return;
    const float* src = (i4 < per) ? Wq : (i4 < 2*per) ? Wk : Wv;
    int j4 = (i4 < per) ? i4 : (i4 < 2*per) ? i4 - per : i4 - 2*per;
    float4 v = ((const float4*)src)[j4];
    __half h0 = __float2half(v.x), h1 = __float2half(v.y);
    __half h2 = __float2half(v.z), h3 = __float2half(v.w);
    __half l0 = __float2half(v.x - __half2float(h0));
    __half l1 = __float2half(v.y - __half2float(h1));
    __half l2 = __float2half(v.z - __half2float(h2));
    __half l3 = __float2half(v.w - __half2float(h3));
    ((__half2*)g_wh)[i4*2]   = __halves2half2(h0, h1);
    ((__half2*)g_wh)[i4*2+1] = __halves2half2(h2, h3);
    ((__half2*)g_wl)[i4*2]   = __halves2half2(l0, l1);
    ((__half2*)g_wl)[i4*2+1] = __halves2half2(l2, l3);
}

// ---------------- kernel 1: QKV projection via fp16x3 tensor-core mma ----------------
// C[m,n] = x[m,:]·W[n&511,:] (+bias); split hi/lo, 3 products, fp32 accum.
#define SROW 24   // halves per smem row (16 data + 8 pad) = 48B: 16B-aligned rows, ldmatrix conflict-free

__device__ __forceinline__ void ldm4(unsigned int addr, unsigned int* r) {
    asm volatile("ldmatrix.sync.aligned.m8n8.x4.shared.b16 {%0,%1,%2,%3}, [%4];"
                 : "=r"(r[0]), "=r"(r[1]), "=r"(r[2]), "=r"(r[3]) : "r"(addr));
}
__device__ __forceinline__ void mma16816(float* c, const unsigned int* a, const unsigned int* b) {
    asm volatile("mma.sync.aligned.m16n8k16.row.col.f32.f16.f16.f32 "
                 "{%0,%1,%2,%3}, {%4,%5,%6,%7}, {%8,%9}, {%0,%1,%2,%3};"
                 : "+f"(c[0]), "+f"(c[1]), "+f"(c[2]), "+f"(c[3])
                 : "r"(a[0]), "r"(a[1]), "r"(a[2]), "r"(a[3]), "r"(b[0]), "r"(b[1]));
}

__global__ __launch_bounds__(256) void gemm_mma(
    const float* __restrict__ bq, const float* __restrict__ bk, const float* __restrict__ bv) {
    __shared__ __align__(16) __half sA[2][2][128 * SROW];   // [buf][hi/lo]  24576 B
    __shared__ __align__(16) __half sB[2][2][128 * SROW];   //               24576 B
    int tid = threadIdx.x, lane = tid & 31, wid = tid >> 5;
    int warpM = wid >> 1, warpN = wid & 1;          // 4x2 warps -> 32x64 per warp
    int m0 = blockIdx.y * 128, n0 = blockIdx.x * 128;
    int w = n0 >> 9;
    const float* bias = (w == 0) ? bq : (w == 1) ? bk : bv;
    float* outp       = (w == 0) ? g_q : (w == 1) ? g_k : g_v;
    int i0 = n0 & 511;

    // global load mapping: row = tid>>1 (0..127), kh = tid&1 -> 8 halves (16B)
    int grow = tid >> 1, gkh = tid & 1;
    const float4* pxh = (const float4*)&g_xh[(size_t)(m0 + grow) * 512 + gkh * 8];
    const float4* pxl = (const float4*)&g_xl[(size_t)(m0 + grow) * 512 + gkh * 8];
    const float4* pwh = (const float4*)&g_wh[(size_t)(w * 512 + i0 + grow) * 512 + gkh * 8];
    const float4* pwl = (const float4*)&g_wl[(size_t)(w * 512 + i0 + grow) * 512 + gkh * 8];
    unsigned int sdst = (unsigned int)(grow * SROW + gkh * 8);   // halves; byte off = grow*48+gkh*16

    float acc[2][8][4];
    #pragma unroll
    for (int i = 0; i < 2; i++)
        #pragma unroll
        for (int j = 0; j < 8; j++)
            #pragma unroll
            for (int c = 0; c < 4; c++) acc[i][j][c] = 0.f;

    float4 rxh, rxl, rwh, rwl;
    // preload slab 0
    rxh = pxh[0]; rxl = pxl[0]; rwh = pwh[0]; rwl = pwl[0];
    *(float4*)&sA[0][0][sdst] = rxh;
    *(float4*)&sA[0][1][sdst] = rxl;
    *(float4*)&sB[0][0][sdst] = rwh;
    *(float4*)&sB[0][1][sdst] = rwl;
    __syncthreads();

    // ldmatrix lane addressing (in halves)
    int aRow = warpM * 32 + (lane & 15), aK = (lane >> 4) * 8;
    int bRow = warpN * 64 + 8 * (lane >> 4) + (lane & 7), bK = ((lane >> 3) & 1) * 8;

    #pragma unroll 1
    for (int ks = 0; ks < 32; ks++) {
        int cur = ks & 1;
        if (ks < 31) {
            int off = (ks + 1) * 2;   // advance 16 halves = 2 float4
            rxh = pxh[off]; rxl = pxl[off]; rwh = pwh[off]; rwl = pwl[off];
        }
        // A fragments: [comp][mt][4]
        unsigned int afr[2][2][4];
        #pragma unroll
        for (int comp = 0; comp < 2; comp++)
            #pragma unroll
            for (int mt = 0; mt < 2; mt++) {
                unsigned int ad = (unsigned int)__cvta_generic_to_shared(
                    &sA[cur][comp][(aRow + mt * 16) * SROW + aK]);
                ldm4(ad, afr[comp][mt]);
            }
        // B pairs + mma
        #pragma unroll
        for (int np = 0; np < 4; np++) {
            unsigned int bfr[2][4];
            #pragma unroll
            for (int comp = 0; comp < 2; comp++) {
                unsigned int bd = (unsigned int)__cvta_generic_to_shared(
                    &sB[cur][comp][(bRow + np * 16) * SROW + bK]);
                ldm4(bd, bfr[comp]);
            }
            #pragma unroll
            for (int mt = 0; mt < 2; mt++) {
                #pragma unroll
                for (int half = 0; half < 2; half++) {
                    int nt = np * 2 + half;
                    unsigned int bh_[2] = {bfr[0][half*2], bfr[0][half*2+1]};
                    unsigned int bl_[2] = {bfr[1][half*2], bfr[1][half*2+1]};
                    mma16816(acc[mt][nt], afr[0][mt], bh_);   // hi*hi
                    mma16816(acc[mt][nt], afr[0][mt], bl_);   // hi*lo
                    mma16816(acc[mt][nt], afr[1][mt], bh_);   // lo*hi
                }
            }
        }
        if (ks < 31) {
            int nxt = cur ^ 1;
            *(float4*)&sA[nxt][0][sdst] = rxh;
            *(float4*)&sA[nxt][1][sdst] = rxl;
            *(float4*)&sB[nxt][0][sdst] = rwh;
            *(float4*)&sB[nxt][1][sdst] = rwl;
            __syncthreads();
        }
    }

    // epilogue
    #pragma unroll
    for (int mt = 0; mt < 2; mt++) {
        int mr = m0 + warpM * 32 + mt * 16 + (lane >> 2);
        #pragma unroll
        for (int nt = 0; nt < 8; nt++) {
            int col = warpN * 64 + nt * 8 + 2 * (lane & 3);
            int i1 = i0 + col, i2 = i1 + 1;
            #pragma unroll
            for (int rh = 0; rh < 2; rh++) {          // rh=0: rows m, rh=1: m+8
                int m = mr + rh * 8;
                int bh_ = (m >> 11) * HH;
                int l = m & 2047;
                float c0 = acc[mt][nt][rh*2], c1 = acc[mt][nt][rh*2+1];
                outp[((((size_t)(bh_ + (i1 >> 6))) << 11) + l) * 64 + (i1 & 63)] = c0 + bias[i1];
                outp[((((size_t)(bh_ + (i2 >> 6))) << 11) + l) * 64 + (i2 & 63)] = c1 + bias[i2];
            }
        }
    }
}

// ---------------- kernel 2: sampled scores -> M ----------------
__global__ void k_sampleM() {
    __shared__ float qsh[4][64];
    int w = threadIdx.x >> 5, lane = threadIdx.x & 31;
    int row = blockIdx.x * 4 + w;
    int bh = row >> 11, l = row & 2047;
    const float* qrow = g_q + ((size_t)row << 6);
    qsh[w][lane] = qrow[lane];
    qsh[w][lane + 32] = qrow[lane + 32];
    __syncwarp();
    const float4* q4 = (const float4*)qsh[w];

    float d0;
    {
        int idx = g_idx[l * SK + lane];
        const float4* kr = (const float4*)(g_k + ((((size_t)bh << 11) + idx) << 6));
        float s = 0.f;
        #pragma unroll
        for (int i = 0; i < 16; i++) {
            float4 a = q4[i], b = kr[i];
            s += a.x*b.x + a.y*b.y + a.z*b.z + a.w*b.w;
        }
        d0 = s;
    }
    float d1 = -INFINITY, s1 = 0.f;
    if (lane < SK - 32) {
        int idx = g_idx[l * SK + 32 + lane];
        const float4* kr = (const float4*)(g_k + ((((size_t)bh << 11) + idx) << 6));
        float s = 0.f;
        #pragma unroll
        for (int i = 0; i < 16; i++) {
            float4 a = q4[i], b = kr[i];
            s += a.x*b.x + a.y*b.y + a.z*b.z + a.w*b.w;
        }
        d1 = s; s1 = s;
    }
    float mx = fmaxf(d0, d1);
    float sm = d0 + s1;
    #pragma unroll
    for (int o = 16; o; o >>= 1) {
        mx = fmaxf(mx, __shfl_xor_sync(0xffffffffu, mx, o));
        sm += __shfl_xor_sync(0xffffffffu, sm, o);
    }
    if (lane == 0) g_M[row] = mx - sm * (1.0f / LL);
}

// ---------------- kernel 3: exact top-40 via radix select (parallel bin scan) ----------------
__global__ void k_topk() {
    __shared__ unsigned int uvals[LL];
    __shared__ int hist[256];
    __shared__ int suf[256];
    __shared__ unsigned int s_prefix;
    __shared__ int s_want, s_slot;
    int bh = blockIdx.x, t = threadIdx.x;
    for (int j = t; j < LL; j += 256) {
        unsigned int b = __float_as_uint(g_M[bh * LL + j]);
        uvals[j] = (b & 0x80000000u) ? ~b : (b | 0x80000000u);
        g_rank[bh * LL + j] = -1;
    }
    if (t == 0) { s_want = UU; s_prefix = 0u; s_slot = 0; }
    __syncthreads();

    #pragma unroll
    for (int level = 0; level < 4; level++) {
        int shift = 24 - level * 8;
        unsigned int mask = (level == 0) ? 0u : (0xFFFFFFFFu << (32 - 8 * level));
        hist[t] = 0;
        __syncthreads();
        unsigned int pref = s_prefix;
        int want = s_want;
        for (int j = t; j < LL; j += 256) {
            unsigned int u = uvals[j];
            if ((u & mask) == pref)
                atomicAdd(&hist[(u >> shift) & 0xFF], 1);
        }
        __syncthreads();
        suf[t] = hist[t];
        __syncthreads();
        #pragma unroll
        for (int o = 1; o < 256; o <<= 1) {
            int v = (t + o < 256) ? suf[t + o] : 0;
            __syncthreads();
            suf[t] += v;
            __syncthreads();
        }
        int above = (t < 255) ? suf[t + 1] : 0;
        if (suf[t] >= want && above < want) {
            s_prefix = pref | ((unsigned int)t << shift);
            s_want = want - above;
        }
        __syncthreads();
    }

    unsigned int T = s_prefix;
    int r = s_want;
    for (int j = t; j < LL; j += 256) {
        unsigned int u = uvals[j];
        bool sel = false;
        if (u > T) sel = true;
        else if (u == T) {
            int rank_eq = 0;
            for (int j2 = 0; j2 < j; j2++) if (uvals[j2] == T) rank_eq++;
            sel = (rank_eq < r);
        }
        if (sel) {
            int slot = atomicAdd(&s_slot, 1);
            g_Mtop[bh * UU + slot] = j;
            g_rank[bh * LL + j] = slot;
        }
    }
}

// ---------------- kernel 4: scores = scale * Qtop @ K^T ----------------
#define KT 64
__global__ void k_scores() {
    __shared__ float qtop[UU * DK];
    __shared__ float kt[KT * 65];
    int bh = blockIdx.y, l0 = blockIdx.x * KT, t = threadIdx.x;
    for (int j = t; j < UU * DK; j += 256) {
        int u = j >> 6, d = j & 63;
        int rl = g_Mtop[bh * UU + u];
        qtop[j] = g_q[((((size_t)bh << 11) + rl) << 6) + d];
    }
    for (int j = t; j < KT * DK; j += 256) {
        int li = j >> 6, d = j & 63;
        kt[li * 65 + d] = g_k[((((size_t)bh << 11) + l0 + li) << 6) + d];
    }
    __syncthreads();
    int lsub = t & 63, ug = t >> 6;
    float accv[10];
    #pragma unroll
    for (int g = 0; g < 10; g++) accv[g] = 0.f;
    for (int d = 0; d < 64; d++) {
        float kv = kt[lsub * 65 + d];
        #pragma unroll
        for (int g = 0; g < 10; g++)
            accv[g] += qtop[(ug + 4 * g) * 64 + d] * kv;
    }
    #pragma unroll
    for (int g = 0; g < 10; g++) {
        int u = ug + 4 * g;
        g_scores[((size_t)(bh * UU + u) << 11) + l0 + lsub] = accv[g] * 0.125f;
    }
}

// ---------------- kernel 5: softmax stats ----------------
__global__ void k_stats() {
    __shared__ float red[256];
    int r = blockIdx.x, t = threadIdx.x;
    const float* s = g_scores + ((size_t)r << 11);
    float mx = -INFINITY;
    for (int j = t; j < LL; j += 256) mx = fmaxf(mx, s[j]);
    red[t] = mx; __syncthreads();
    for (int o = 128; o; o >>= 1) { if (t < o) red[t] = fmaxf(red[t], red[t + o]); __syncthreads(); }
    mx = red[0]; __syncthreads();
    float sm = 0.f;
    for (int j = t; j < LL; j += 256) sm += expf(s[j] - mx);
    red[t] = sm; __syncthreads();
    for (int o = 128; o; o >>= 1) { if (t < o) red[t] += red[t + o]; __syncthreads(); }
    if (t == 0) { g_mx[r] = mx; g_inv[r] = 1.0f / red[0]; }
}

// ---------------- cumsum (context) ----------------
__global__ void k_csum_part() {
    __shared__ float red[256];
    int blk = blockIdx.x;
    int bh = blk >> 4, c = blk & 15;
    int t = threadIdx.x, d = t & 63, p = t >> 6;
    const float* vb = g_v + ((((size_t)bh << 11) + c * CH) << 6);
    float s = 0.f;
    for (int i = 0; i < 32; i++) s += vb[(p * 32 + i) * 64 + d];
    red[t] = s; __syncthreads();
    if (t < 64)
        g_part[blk * 64 + t] = red[t] + red[t + 64] + red[t + 128] + red[t + 192];
}

__global__ void k_csum_off() {
    int bh = blockIdx.x, d = threadIdx.x;
    float run = 0.f;
    for (int c = 0; c < NCH; c++) {
        g_offs[(bh * NCH + c) * 64 + d] = run;
        run += g_part[(bh * NCH + c) * 64 + d];
    }
}

__global__ void k_csum_scan(float* __restrict__ ctx) {
    __shared__ float vsh[CH * 64];
    int blk = blockIdx.x;
    int bh = blk >> 4, c = blk & 15;
    int t = threadIdx.x;
    const float4* vb = (const float4*)(g_v + ((((size_t)bh << 11) + c * CH) << 6));
    float4* vs4 = (float4*)vsh;
    for (int j = t; j < CH * 16; j += 256) vs4[j] = vb[j];
    __syncthreads();
    if (t < 64) {
        float run = g_offs[(bh * NCH + c) * 64 + t];
        for (int i = 0; i < CH; i++) { run += vsh[i * 64 + t]; vsh[i * 64 + t] = run; }
    }
    __syncthreads();
    float4* ob = (float4*)(ctx + ((((size_t)bh << 11) + c * CH) << 6));
    for (int j = t; j < CH * 16; j += 256) ob[j] = vs4[j];
}

// ---------------- kernel 7: upd partials = attn @ V ----------------
__global__ void k_upd() {
    __shared__ float vsh[64 * 64];
    __shared__ float ash[UU * 64];
    __shared__ float smx[UU], sinv[UU];
    int bh = blockIdx.y, ls = blockIdx.x;
    int t = threadIdx.x;
    if (t < UU) { smx[t] = g_mx[bh * UU + t]; sinv[t] = g_inv[bh * UU + t]; }

    int lane2 = (t & 31) * 2, ug = t >> 5;
    float acc[5][2];
    #pragma unroll
    for (int uu = 0; uu < 5; uu++) { acc[uu][0] = 0.f; acc[uu][1] = 0.f; }

    for (int tile = 0; tile < 4; tile++) {
        int l0 = ls * 256 + tile * 64;
        __syncthreads();
        const float4* vb = (const float4*)(g_v + ((((size_t)bh << 11) + l0) << 6));
        float4* vs4 = (float4*)vsh;
        for (int j = t; j < 64 * 16; j += 256) vs4[j] = vb[j];
        for (int j = t; j < UU * 64; j += 256) {
            int u = j >> 6, li = j & 63;
            ash[j] = expf(g_scores[((size_t)(bh * UU + u) << 11) + l0 + li] - smx[u]) * sinv[u];
        }
        __syncthreads();
        for (int li = 0; li < 64; li++) {
            float v0 = vsh[li * 64 + lane2], v1 = vsh[li * 64 + lane2 + 1];
            #pragma unroll
            for (int uu = 0; uu < 5; uu++) {
                float a = ash[(ug * 5 + uu) * 64 + li];
                acc[uu][0] += a * v0;
                acc[uu][1] += a * v1;
            }
        }
    }
    #pragma unroll
    for (int uu = 0; uu < 5; uu++) {
        int r = bh * UU + ug * 5 + uu;
        g_updp[((size_t)ls * BH * UU + r) * 64 + lane2]     = acc[uu][0];
        g_updp[((size_t)ls * BH * UU + r) * 64 + lane2 + 1] = acc[uu][1];
    }
}

// ---------------- kernel 8: reduce upd partials + scatter into context ----------------
__global__ void k_scatter(float* __restrict__ ctx) {
    int r = blockIdx.x, d = threadIdx.x;
    int bh = r / UU;
    int l = g_Mtop[r];
    float s = 0.f;
    #pragma unroll
    for (int p = 0; p < 8; p++) s += g_updp[((size_t)p * BH * UU + r) * 64 + d];
    ctx[((((size_t)bh << 11) + l) << 6) + d] = s;
}

// ---------------- kernel 9: attns output ----------------
__global__ void k_attns(float* __restrict__ attns) {
    int row = blockIdx.x;
    int bh = row >> 11;
    int r = g_rank[row];
    float* out = attns + ((size_t)row << 11);
    int t = threadIdx.x;
    if (r < 0) {
        float4 c = make_float4(1.0f / LL, 1.0f / LL, 1.0f / LL, 1.0f / LL);
        float4* o4 = (float4*)out;
        o4[t] = c;
        o4[t + 256] = c;
    } else {
        float mx = g_mx[bh * UU + r], inv = g_inv[bh * UU + r];
        const float* s = g_scores + ((size_t)(bh * UU + r) << 11);
        #pragma unroll
        for (int j = 0; j < 2; j++) {
            int base = (t + j * 256) * 4;
            float4 sv = *(const float4*)(s + base);
            float4 ov;
            ov.x = expf(sv.x - mx) * inv;
            ov.y = expf(sv.y - mx) * inv;
            ov.z = expf(sv.z - mx) * inv;
            ov.w = expf(sv.w - mx) * inv;
            *(float4*)(out + base) = ov;
        }
    }
}

// ---------------- launch ----------------
extern "C" void kernel_launch(void* const* d_in, const int* in_sizes, int n_in,
                              void* d_out, int out_size) {
    const float* x  = (const float*)d_in[0];
    const float* Wq = (const float*)d_in[1];
    const float* bq = (const float*)d_in[2];
    const float* Wk = (const float*)d_in[3];
    const float* bk = (const float*)d_in[4];
    const float* Wv = (const float*)d_in[5];
    const float* bv = (const float*)d_in[6];
    const unsigned int* idxraw = (const unsigned int*)d_in[7];

    float* ctx   = (float*)d_out;
    float* attns = ctx + (size_t)BB * LL * DD;

    k_idx<<<1, 1024>>>(idxraw, LL * SK);
    k_cvt_x<<<(BB*LL*DD/4 + 255)/256, 256>>>(x);
    k_cvt_w<<<(3*DD*DD/4 + 255)/256, 256>>>(Wq, Wk, Wv);
    gemm_mma<<<dim3(12, 32), 256>>>(bq, bk, bv);     // profiled slot (4th launch)
    k_sampleM<<<NROWS / 4, 128>>>();
    k_topk<<<BH, 256>>>();
    k_scores<<<dim3(LL / KT, BH), 256>>>();
    k_stats<<<BH * UU, 256>>>();
    k_csum_part<<<BH * NCH, 256>>>();
    k_csum_off<<<BH, 64>>>();
    k_csum_scan<<<BH * NCH, 256>>>(ctx);
    k_upd<<<dim3(8, BH), 256>>>();
    k_scatter<<<BH * UU, 64>>>(ctx);
    k_attns<<<NROWS, 256>>>(attns);
}

// round 6
// speedup vs baseline: 1.4382x; 1.0823x over previous
#include <cuda_runtime.h>
#include <cuda_fp16.h>
#include <math.h>

#define BB 2
#define LL 2048
#define DD 512
#define HH 8
#define DK 64
#define SK 40
#define UU 40
#define BH 16            // BB*HH
#define NROWS 32768      // BH*LL
#define NCH 16           // cumsum chunks per (b,h)
#define CH 128           // L per chunk

// ---------------- scratch (device globals; no allocation) ----------------
__device__ float g_q[BB*HH*LL*DK];
__device__ float g_k[BB*HH*LL*DK];
__device__ float g_v[BB*HH*LL*DK];
__device__ float g_scores[BH*UU*LL];
__device__ float g_M[NROWS];
__device__ int   g_Mtop[BH*UU];
__device__ int   g_rank[NROWS];
__device__ float g_mx[BH*UU];
__device__ float g_inv[BH*UU];
__device__ float g_part[BH*NCH*DK];
__device__ float g_offs[BH*NCH*DK];
__device__ float g_updp[8*BH*UU*DK];
__device__ int   g_idx[LL*SK];
// fp16x3 split operands (16B-aligned for float4 access)
__device__ __align__(16) __half g_xh[BB*LL*DD];
__device__ __align__(16) __half g_xl[BB*LL*DD];
__device__ __align__(16) __half g_wh[3*DD*DD];
__device__ __align__(16) __half g_wl[3*DD*DD];

// ---------------- kernel 0: normalize index_sample (int32 vs int64) ----------------
__global__ void k_idx(const unsigned int* __restrict__ raw, int nelem) {
    __shared__ int s_flag;
    if (threadIdx.x == 0) s_flag = 0;
    __syncthreads();
    int local = 0;
    for (int j = threadIdx.x * 2 + 1; j < nelem; j += blockDim.x * 2)
        if (raw[j] != 0u) local = 1;
    if (local) atomicOr(&s_flag, 1);
    __syncthreads();
    int is32 = s_flag;
    for (int e = threadIdx.x; e < nelem; e += blockDim.x)
        g_idx[e] = is32 ? (int)raw[e] : (int)raw[2 * e];
}

// ---------------- fp16 hi/lo split converters ----------------
__global__ void k_cvt_x(const float* __restrict__ x) {
    int i4 = blockIdx.x * blockDim.x + threadIdx.x;     // 4 elems each
    if (i4 >= BB*LL*DD/4) return;
    float4 v = ((const float4*)x)[i4];
    __half h0 = __float2half(v.x), h1 = __float2half(v.y);
    __half h2 = __float2half(v.z), h3 = __float2half(v.w);
    __half l0 = __float2half(v.x - __half2float(h0));
    __half l1 = __float2half(v.y - __half2float(h1));
    __half l2 = __float2half(v.z - __half2float(h2));
    __half l3 = __float2half(v.w - __half2float(h3));
    ((__half2*)g_xh)[i4*2]   = __halves2half2(h0, h1);
    ((__half2*)g_xh)[i4*2+1] = __halves2half2(h2, h3);
    ((__half2*)g_xl)[i4*2]   = __halves2half2(l0, l1);
    ((__half2*)g_xl)[i4*2+1] = __halves2half2(l2, l3);
}

__global__ void k_cvt_w(const float* __restrict__ Wq, const float* __restrict__ Wk,
                        const float* __restrict__ Wv) {
    int i4 = blockIdx.x * blockDim.x + threadIdx.x;
    int per = DD*DD/4;
    if (i4 >= 3*per) return;
    const float* src = (i4 < per) ? Wq : (i4 < 2*per) ? Wk : Wv;
    int j4 = (i4 < per) ? i4 : (i4 < 2*per) ? i4 - per : i4 - 2*per;
    float4 v = ((const float4*)src)[j4];
    __half h0 = __float2half(v.x), h1 = __float2half(v.y);
    __half h2 = __float2half(v.z), h3 = __float2half(v.w);
    __half l0 = __float2half(v.x - __half2float(h0));
    __half l1 = __float2half(v.y - __half2float(h1));
    __half l2 = __float2half(v.z - __half2float(h2));
    __half l3 = __float2half(v.w - __half2float(h3));
    ((__half2*)g_wh)[i4*2]   = __halves2half2(h0, h1);
    ((__half2*)g_wh)[i4*2+1] = __halves2half2(h2, h3);
    ((__half2*)g_wl)[i4*2]   = __halves2half2(l0, l1);
    ((__half2*)g_wl)[i4*2+1] = __halves2half2(l2, l3);
}

// ---------------- kernel 1: QKV projection via fp16x3 tensor-core mma ----------------
#define SROW 24   // halves per smem row (16 data + 8 pad) = 48B

#define CP_ASYNC16(dst, src) \
    asm volatile("cp.async.ca.shared.global [%0], [%1], 16;" :: "r"(dst), "l"(src))
#define CP_COMMIT() asm volatile("cp.async.commit_group;")
#define CP_WAIT1()  asm volatile("cp.async.wait_group 1;")

__device__ __forceinline__ void ldm4(unsigned int addr, unsigned int* r) {
    asm volatile("ldmatrix.sync.aligned.m8n8.x4.shared.b16 {%0,%1,%2,%3}, [%4];"
                 : "=r"(r[0]), "=r"(r[1]), "=r"(r[2]), "=r"(r[3]) : "r"(addr));
}
__device__ __forceinline__ void mma16816(float* c, const unsigned int* a, const unsigned int* b) {
    asm volatile("mma.sync.aligned.m16n8k16.row.col.f32.f16.f16.f32 "
                 "{%0,%1,%2,%3}, {%4,%5,%6,%7}, {%8,%9}, {%0,%1,%2,%3};"
                 : "+f"(c[0]), "+f"(c[1]), "+f"(c[2]), "+f"(c[3])
                 : "r"(a[0]), "r"(a[1]), "r"(a[2]), "r"(a[3]), "r"(b[0]), "r"(b[1]));
}

#define COMPSZ (128 * SROW * 2)     // bytes per [comp] plane: 6144
#define STAGESZ (2 * COMPSZ)        // bytes per stage (hi+lo): 12288

__global__ __launch_bounds__(256, 2) void gemm_mma(
    const float* __restrict__ bq, const float* __restrict__ bk, const float* __restrict__ bv) {
    __shared__ __align__(16) __half sA[2][2][128 * SROW];   // [stage][hi/lo] 24576 B
    __shared__ __align__(16) __half sB[2][2][128 * SROW];   //                24576 B
    int tid = threadIdx.x, lane = tid & 31, wid = tid >> 5;
    int warpM = wid >> 1, warpN = wid & 1;          // 4x2 warps -> 32x64 per warp
    int m0 = blockIdx.y * 128, n0 = blockIdx.x * 128;
    int w = n0 >> 9;
    const float* bias = (w == 0) ? bq : (w == 1) ? bk : bv;
    float* outp       = (w == 0) ? g_q : (w == 1) ? g_k : g_v;
    int i0 = n0 & 511;

    // global load mapping: row = tid>>1 (0..127), kh = tid&1 -> 8 halves (16B)
    int grow = tid >> 1, gkh = tid & 1;
    const __half* pxh = &g_xh[(size_t)(m0 + grow) * 512 + gkh * 8];
    const __half* pxl = &g_xl[(size_t)(m0 + grow) * 512 + gkh * 8];
    const __half* pwh = &g_wh[(size_t)(w * 512 + i0 + grow) * 512 + gkh * 8];
    const __half* pwl = &g_wl[(size_t)(w * 512 + i0 + grow) * 512 + gkh * 8];
    unsigned int dst_off = (unsigned int)((grow * SROW + gkh * 8) * 2);  // bytes
    unsigned int baseA = (unsigned int)__cvta_generic_to_shared(&sA[0][0][0]);
    unsigned int baseB = (unsigned int)__cvta_generic_to_shared(&sB[0][0][0]);

    float acc[2][8][4];
    #pragma unroll
    for (int i = 0; i < 2; i++)
        #pragma unroll
        for (int j = 0; j < 8; j++)
            #pragma unroll
            for (int c = 0; c < 4; c++) acc[i][j][c] = 0.f;

    // prologue: stages 0,1 in flight
    #pragma unroll
    for (int s = 0; s < 2; s++) {
        unsigned int sa = baseA + s * STAGESZ + dst_off;
        unsigned int sb = baseB + s * STAGESZ + dst_off;
        CP_ASYNC16(sa,          pxh + s * 16);
        CP_ASYNC16(sa + COMPSZ, pxl + s * 16);
        CP_ASYNC16(sb,          pwh + s * 16);
        CP_ASYNC16(sb + COMPSZ, pwl + s * 16);
        CP_COMMIT();
    }

    // ldmatrix lane addressing (in halves)
    int aRow = warpM * 32 + (lane & 15), aK = (lane >> 4) * 8;
    int bRow = warpN * 64 + 8 * (lane >> 4) + (lane & 7), bK = ((lane >> 3) & 1) * 8;

    #pragma unroll 1
    for (int ks = 0; ks < 32; ks++) {
        int cur = ks & 1;
        CP_WAIT1();
        __syncthreads();

        // A fragments: [comp][mt][4]
        unsigned int afr[2][2][4];
        #pragma unroll
        for (int comp = 0; comp < 2; comp++)
            #pragma unroll
            for (int mt = 0; mt < 2; mt++) {
                unsigned int ad = (unsigned int)__cvta_generic_to_shared(
                    &sA[cur][comp][(aRow + mt * 16) * SROW + aK]);
                ldm4(ad, afr[comp][mt]);
            }
        #pragma unroll
        for (int np = 0; np < 4; np++) {
            unsigned int bfr[2][4];
            #pragma unroll
            for (int comp = 0; comp < 2; comp++) {
                unsigned int bd = (unsigned int)__cvta_generic_to_shared(
                    &sB[cur][comp][(bRow + np * 16) * SROW + bK]);
                ldm4(bd, bfr[comp]);
            }
            #pragma unroll
            for (int mt = 0; mt < 2; mt++) {
                #pragma unroll
                for (int half = 0; half < 2; half++) {
                    int nt = np * 2 + half;
                    unsigned int bh_[2] = {bfr[0][half*2], bfr[0][half*2+1]};
                    unsigned int bl_[2] = {bfr[1][half*2], bfr[1][half*2+1]};
                    mma16816(acc[mt][nt], afr[0][mt], bh_);   // hi*hi
                    mma16816(acc[mt][nt], afr[0][mt], bl_);   // hi*lo
                    mma16816(acc[mt][nt], afr[1][mt], bh_);   // lo*hi
                }
            }
        }

        __syncthreads();   // all warps done reading 'cur' before refill
        if (ks + 2 < 32) {
            unsigned int sa = baseA + cur * STAGESZ + dst_off;
            unsigned int sb = baseB + cur * STAGESZ + dst_off;
            CP_ASYNC16(sa,          pxh + (ks + 2) * 16);
            CP_ASYNC16(sa + COMPSZ, pxl + (ks + 2) * 16);
            CP_ASYNC16(sb,          pwh + (ks + 2) * 16);
            CP_ASYNC16(sb + COMPSZ, pwl + (ks + 2) * 16);
        }
        CP_COMMIT();       // commit (possibly empty) group to keep wait counts aligned
    }

    // epilogue
    #pragma unroll
    for (int mt = 0; mt < 2; mt++) {
        int mr = m0 + warpM * 32 + mt * 16 + (lane >> 2);
        #pragma unroll
        for (int nt = 0; nt < 8; nt++) {
            int col = warpN * 64 + nt * 8 + 2 * (lane & 3);
            int i1 = i0 + col, i2 = i1 + 1;
            #pragma unroll
            for (int rh = 0; rh < 2; rh++) {
                int m = mr + rh * 8;
                int bh_ = (m >> 11) * HH;
                int l = m & 2047;
                float c0 = acc[mt][nt][rh*2], c1 = acc[mt][nt][rh*2+1];
                outp[((((size_t)(bh_ + (i1 >> 6))) << 11) + l) * 64 + (i1 & 63)] = c0 + bias[i1];
                outp[((((size_t)(bh_ + (i2 >> 6))) << 11) + l) * 64 + (i2 & 63)] = c1 + bias[i2];
            }
        }
    }
}

// ---------------- kernel 2: sampled scores -> M ----------------
__global__ void k_sampleM() {
    __shared__ float qsh[4][64];
    int w = threadIdx.x >> 5, lane = threadIdx.x & 31;
    int row = blockIdx.x * 4 + w;
    int bh = row >> 11, l = row & 2047;
    const float* qrow = g_q + ((size_t)row << 6);
    qsh[w][lane] = qrow[lane];
    qsh[w][lane + 32] = qrow[lane + 32];
    __syncwarp();
    const float4* q4 = (const float4*)qsh[w];

    float d0;
    {
        int idx = g_idx[l * SK + lane];
        const float4* kr = (const float4*)(g_k + ((((size_t)bh << 11) + idx) << 6));
        float s = 0.f;
        #pragma unroll
        for (int i = 0; i < 16; i++) {
            float4 a = q4[i], b = kr[i];
            s += a.x*b.x + a.y*b.y + a.z*b.z + a.w*b.w;
        }
        d0 = s;
    }
    float d1 = -INFINITY, s1 = 0.f;
    if (lane < SK - 32) {
        int idx = g_idx[l * SK + 32 + lane];
        const float4* kr = (const float4*)(g_k + ((((size_t)bh << 11) + idx) << 6));
        float s = 0.f;
        #pragma unroll
        for (int i = 0; i < 16; i++) {
            float4 a = q4[i], b = kr[i];
            s += a.x*b.x + a.y*b.y + a.z*b.z + a.w*b.w;
        }
        d1 = s; s1 = s;
    }
    float mx = fmaxf(d0, d1);
    float sm = d0 + s1;
    #pragma unroll
    for (int o = 16; o; o >>= 1) {
        mx = fmaxf(mx, __shfl_xor_sync(0xffffffffu, mx, o));
        sm += __shfl_xor_sync(0xffffffffu, sm, o);
    }
    if (lane == 0) g_M[row] = mx - sm * (1.0f / LL);
}

// ---------------- kernel 3: exact top-40 via radix select (parallel bin scan) ----------------
__global__ void k_topk() {
    __shared__ unsigned int uvals[LL];
    __shared__ int hist[256];
    __shared__ int suf[256];
    __shared__ unsigned int s_prefix;
    __shared__ int s_want, s_slot;
    int bh = blockIdx.x, t = threadIdx.x;
    for (int j = t; j < LL; j += 256) {
        unsigned int b = __float_as_uint(g_M[bh * LL + j]);
        uvals[j] = (b & 0x80000000u) ? ~b : (b | 0x80000000u);
        g_rank[bh * LL + j] = -1;
    }
    if (t == 0) { s_want = UU; s_prefix = 0u; s_slot = 0; }
    __syncthreads();

    #pragma unroll
    for (int level = 0; level < 4; level++) {
        int shift = 24 - level * 8;
        unsigned int mask = (level == 0) ? 0u : (0xFFFFFFFFu << (32 - 8 * level));
        hist[t] = 0;
        __syncthreads();
        unsigned int pref = s_prefix;
        int want = s_want;
        for (int j = t; j < LL; j += 256) {
            unsigned int u = uvals[j];
            if ((u & mask) == pref)
                atomicAdd(&hist[(u >> shift) & 0xFF], 1);
        }
        __syncthreads();
        suf[t] = hist[t];
        __syncthreads();
        #pragma unroll
        for (int o = 1; o < 256; o <<= 1) {
            int v = (t + o < 256) ? suf[t + o] : 0;
            __syncthreads();
            suf[t] += v;
            __syncthreads();
        }
        int above = (t < 255) ? suf[t + 1] : 0;
        if (suf[t] >= want && above < want) {
            s_prefix = pref | ((unsigned int)t << shift);
            s_want = want - above;
        }
        __syncthreads();
    }

    unsigned int T = s_prefix;
    int r = s_want;
    for (int j = t; j < LL; j += 256) {
        unsigned int u = uvals[j];
        bool sel = false;
        if (u > T) sel = true;
        else if (u == T) {
            int rank_eq = 0;
            for (int j2 = 0; j2 < j; j2++) if (uvals[j2] == T) rank_eq++;
            sel = (rank_eq < r);
        }
        if (sel) {
            int slot = atomicAdd(&s_slot, 1);
            g_Mtop[bh * UU + slot] = j;
            g_rank[bh * LL + j] = slot;
        }
    }
}

// ---------------- kernel 4: scores = scale * Qtop @ K^T ----------------
#define KT 64
__global__ void k_scores() {
    __shared__ float qtop[UU * DK];
    __shared__ float kt[KT * 65];
    int bh = blockIdx.y, l0 = blockIdx.x * KT, t = threadIdx.x;
    for (int j = t; j < UU * DK; j += 256) {
        int u = j >> 6, d = j & 63;
        int rl = g_Mtop[bh * UU + u];
        qtop[j] = g_q[((((size_t)bh << 11) + rl) << 6) + d];
    }
    for (int j = t; j < KT * DK; j += 256) {
        int li = j >> 6, d = j & 63;
        kt[li * 65 + d] = g_k[((((size_t)bh << 11) + l0 + li) << 6) + d];
    }
    __syncthreads();
    int lsub = t & 63, ug = t >> 6;
    float accv[10];
    #pragma unroll
    for (int g = 0; g < 10; g++) accv[g] = 0.f;
    for (int d = 0; d < 64; d++) {
        float kv = kt[lsub * 65 + d];
        #pragma unroll
        for (int g = 0; g < 10; g++)
            accv[g] += qtop[(ug + 4 * g) * 64 + d] * kv;
    }
    #pragma unroll
    for (int g = 0; g < 10; g++) {
        int u = ug + 4 * g;
        g_scores[((size_t)(bh * UU + u) << 11) + l0 + lsub] = accv[g] * 0.125f;
    }
}

// ---------------- kernel 5: softmax stats ----------------
__global__ void k_stats() {
    __shared__ float red[256];
    int r = blockIdx.x, t = threadIdx.x;
    const float* s = g_scores + ((size_t)r << 11);
    float mx = -INFINITY;
    for (int j = t; j < LL; j += 256) mx = fmaxf(mx, s[j]);
    red[t] = mx; __syncthreads();
    for (int o = 128; o; o >>= 1) { if (t < o) red[t] = fmaxf(red[t], red[t + o]); __syncthreads(); }
    mx = red[0]; __syncthreads();
    float sm = 0.f;
    for (int j = t; j < LL; j += 256) sm += expf(s[j] - mx);
    red[t] = sm; __syncthreads();
    for (int o = 128; o; o >>= 1) { if (t < o) red[t] += red[t + o]; __syncthreads(); }
    if (t == 0) { g_mx[r] = mx; g_inv[r] = 1.0f / red[0]; }
}

// ---------------- cumsum (context) ----------------
__global__ void k_csum_part() {
    __shared__ float red[256];
    int blk = blockIdx.x;
    int bh = blk >> 4, c = blk & 15;
    int t = threadIdx.x, d = t & 63, p = t >> 6;
    const float* vb = g_v + ((((size_t)bh << 11) + c * CH) << 6);
    float s = 0.f;
    for (int i = 0; i < 32; i++) s += vb[(p * 32 + i) * 64 + d];
    red[t] = s; __syncthreads();
    if (t < 64)
        g_part[blk * 64 + t] = red[t] + red[t + 64] + red[t + 128] + red[t + 192];
}

__global__ void k_csum_off() {
    int bh = blockIdx.x, d = threadIdx.x;
    float run = 0.f;
    for (int c = 0; c < NCH; c++) {
        g_offs[(bh * NCH + c) * 64 + d] = run;
        run += g_part[(bh * NCH + c) * 64 + d];
    }
}

__global__ void k_csum_scan(float* __restrict__ ctx) {
    __shared__ float vsh[CH * 64];
    int blk = blockIdx.x;
    int bh = blk >> 4, c = blk & 15;
    int t = threadIdx.x;
    const float4* vb = (const float4*)(g_v + ((((size_t)bh << 11) + c * CH) << 6));
    float4* vs4 = (float4*)vsh;
    for (int j = t; j < CH * 16; j += 256) vs4[j] = vb[j];
    __syncthreads();
    if (t < 64) {
        float run = g_offs[(bh * NCH + c) * 64 + t];
        for (int i = 0; i < CH; i++) { run += vsh[i * 64 + t]; vsh[i * 64 + t] = run; }
    }
    __syncthreads();
    float4* ob = (float4*)(ctx + ((((size_t)bh << 11) + c * CH) << 6));
    for (int j = t; j < CH * 16; j += 256) ob[j] = vs4[j];
}

// ---------------- kernel 7: upd partials = attn @ V ----------------
__global__ void k_upd() {
    __shared__ float vsh[64 * 64];
    __shared__ float ash[UU * 64];
    __shared__ float smx[UU], sinv[UU];
    int bh = blockIdx.y, ls = blockIdx.x;
    int t = threadIdx.x;
    if (t < UU) { smx[t] = g_mx[bh * UU + t]; sinv[t] = g_inv[bh * UU + t]; }

    int lane2 = (t & 31) * 2, ug = t >> 5;
    float acc[5][2];
    #pragma unroll
    for (int uu = 0; uu < 5; uu++) { acc[uu][0] = 0.f; acc[uu][1] = 0.f; }

    for (int tile = 0; tile < 4; tile++) {
        int l0 = ls * 256 + tile * 64;
        __syncthreads();
        const float4* vb = (const float4*)(g_v + ((((size_t)bh << 11) + l0) << 6));
        float4* vs4 = (float4*)vsh;
        for (int j = t; j < 64 * 16; j += 256) vs4[j] = vb[j];
        for (int j = t; j < UU * 64; j += 256) {
            int u = j >> 6, li = j & 63;
            ash[j] = expf(g_scores[((size_t)(bh * UU + u) << 11) + l0 + li] - smx[u]) * sinv[u];
        }
        __syncthreads();
        for (int li = 0; li < 64; li++) {
            float v0 = vsh[li * 64 + lane2], v1 = vsh[li * 64 + lane2 + 1];
            #pragma unroll
            for (int uu = 0; uu < 5; uu++) {
                float a = ash[(ug * 5 + uu) * 64 + li];
                acc[uu][0] += a * v0;
                acc[uu][1] += a * v1;
            }
        }
    }
    #pragma unroll
    for (int uu = 0; uu < 5; uu++) {
        int r = bh * UU + ug * 5 + uu;
        g_updp[((size_t)ls * BH * UU + r) * 64 + lane2]     = acc[uu][0];
        g_updp[((size_t)ls * BH * UU + r) * 64 + lane2 + 1] = acc[uu][1];
    }
}

// ---------------- kernel 8: reduce upd partials + scatter into context ----------------
__global__ void k_scatter(float* __restrict__ ctx) {
    int r = blockIdx.x, d = threadIdx.x;
    int bh = r / UU;
    int l = g_Mtop[r];
    float s = 0.f;
    #pragma unroll
    for (int p = 0; p < 8; p++) s += g_updp[((size_t)p * BH * UU + r) * 64 + d];
    ctx[((((size_t)bh << 11) + l) << 6) + d] = s;
}

// ---------------- kernel 9: attns output ----------------
__global__ void k_attns(float* __restrict__ attns) {
    int row = blockIdx.x;
    int bh = row >> 11;
    int r = g_rank[row];
    float* out = attns + ((size_t)row << 11);
    int t = threadIdx.x;
    if (r < 0) {
        float4 c = make_float4(1.0f / LL, 1.0f / LL, 1.0f / LL, 1.0f / LL);
        float4* o4 = (float4*)out;
        o4[t] = c;
        o4[t + 256] = c;
    } else {
        float mx = g_mx[bh * UU + r], inv = g_inv[bh * UU + r];
        const float* s = g_scores + ((size_t)(bh * UU + r) << 11);
        #pragma unroll
        for (int j = 0; j < 2; j++) {
            int base = (t + j * 256) * 4;
            float4 sv = *(const float4*)(s + base);
            float4 ov;
            ov.x = expf(sv.x - mx) * inv;
            ov.y = expf(sv.y - mx) * inv;
            ov.z = expf(sv.z - mx) * inv;
            ov.w = expf(sv.w - mx) * inv;
            *(float4*)(out + base) = ov;
        }
    }
}

// ---------------- launch ----------------
extern "C" void kernel_launch(void* const* d_in, const int* in_sizes, int n_in,
                              void* d_out, int out_size) {
    const float* x  = (const float*)d_in[0];
    const float* Wq = (const float*)d_in[1];
    const float* bq = (const float*)d_in[2];
    const float* Wk = (const float*)d_in[3];
    const float* bk = (const float*)d_in[4];
    const float* Wv = (const float*)d_in[5];
    const float* bv = (const float*)d_in[6];
    const unsigned int* idxraw = (const unsigned int*)d_in[7];

    float* ctx   = (float*)d_out;
    float* attns = ctx + (size_t)BB * LL * DD;

    k_idx<<<1, 1024>>>(idxraw, LL * SK);
    k_cvt_x<<<(BB*LL*DD/4 + 255)/256, 256>>>(x);
    k_cvt_w<<<(3*DD*DD/4 + 255)/256, 256>>>(Wq, Wk, Wv);
    gemm_mma<<<dim3(12, 32), 256>>>(bq, bk, bv);     // profiled slot (4th launch)
    k_sampleM<<<NROWS / 4, 128>>>();
    k_topk<<<BH, 256>>>();
    k_scores<<<dim3(LL / KT, BH), 256>>>();
    k_stats<<<BH * UU, 256>>>();
    k_csum_part<<<BH * NCH, 256>>>();
    k_csum_off<<<BH, 64>>>();
    k_csum_scan<<<BH * NCH, 256>>>(ctx);
    k_upd<<<dim3(8, BH), 256>>>();
    k_scatter<<<BH * UU, 64>>>(ctx);
    k_attns<<<NROWS, 256>>>(attns);
}

// round 7
// speedup vs baseline: 1.5962x; 1.1098x over previous
#include <cuda_runtime.h>
#include <cuda_fp16.h>
#include <math.h>

#define BB 2
#define LL 2048
#define DD 512
#define HH 8
#define DK 64
#define SK 40
#define UU 40
#define BH 16            // BB*HH
#define NROWS 32768      // BH*LL
#define NCH 16           // cumsum chunks per (b,h)
#define CH 128           // L per chunk

// ---------------- scratch (device globals; no allocation) ----------------
__device__ float g_q[BB*HH*LL*DK];
__device__ float g_k[BB*HH*LL*DK];
__device__ float g_v[BB*HH*LL*DK];
__device__ float g_scores[BH*UU*LL];
__device__ float g_M[NROWS];
__device__ int   g_Mtop[BH*UU];
__device__ int   g_rank[NROWS];
__device__ float g_mx[BH*UU];
__device__ float g_inv[BH*UU];
__device__ float g_part[BH*NCH*DK];
__device__ float g_offs[BH*NCH*DK];
__device__ float g_updp[8*BH*UU*DK];
__device__ int   g_idx[LL*SK];
// fp16x3 split operands (16B-aligned for float4 access)
__device__ __align__(16) __half g_xh[BB*LL*DD];
__device__ __align__(16) __half g_xl[BB*LL*DD];
__device__ __align__(16) __half g_wh[3*DD*DD];
__device__ __align__(16) __half g_wl[3*DD*DD];

// ---------------- kernel 0: normalize index_sample (int32 vs int64), 16 blocks ----------------
__global__ void k_idx(const unsigned int* __restrict__ raw, int nelem) {
    __shared__ int s_flag;
    int per = nelem / gridDim.x;               // elements AND inspected words per block
    int wbase = blockIdx.x * per;              // even (per is even)
    if (threadIdx.x == 0) s_flag = 0;
    __syncthreads();
    // Inspect odd words within the first nelem words (valid for both widths).
    int local = 0;
    for (int j = threadIdx.x * 2 + 1; j < per; j += blockDim.x * 2)
        if (raw[wbase + j] != 0u) local = 1;   // int64: hi-words all zero; int32: real values
    if (local) atomicOr(&s_flag, 1);
    __syncthreads();
    int is32 = s_flag;
    int ebase = blockIdx.x * per;
    for (int e = ebase + threadIdx.x; e < ebase + per; e += blockDim.x)
        g_idx[e] = is32 ? (int)raw[e] : (int)raw[2 * e];
}

// ---------------- fused fp16 hi/lo split converter (x then W) ----------------
__global__ void k_cvt(const float* __restrict__ x, const float* __restrict__ Wq,
                      const float* __restrict__ Wk, const float* __restrict__ Wv) {
    const int NX = BB*LL*DD/4;     // x quarters
    const int PW = DD*DD/4;        // per-W quarters
    int i4 = blockIdx.x * blockDim.x + threadIdx.x;
    const float* src;
    __half2 *dh, *dl;
    int j4;
    if (i4 < NX) {
        src = x; j4 = i4;
        dh = (__half2*)g_xh + i4*2; dl = (__half2*)g_xl + i4*2;
    } else {
        int k = i4 - NX;
        if (k >= 3*PW) return;
        src = (k < PW) ? Wq : (k < 2*PW) ? Wk : Wv;
        j4  = (k < PW) ? k  : (k < 2*PW) ? k - PW : k - 2*PW;
        dh = (__half2*)g_wh + k*2; dl = (__half2*)g_wl + k*2;
    }
    float4 v = ((const float4*)src)[j4];
    __half h0 = __float2half(v.x), h1 = __float2half(v.y);
    __half h2 = __float2half(v.z), h3 = __float2half(v.w);
    __half l0 = __float2half(v.x - __half2float(h0));
    __half l1 = __float2half(v.y - __half2float(h1));
    __half l2 = __float2half(v.z - __half2float(h2));
    __half l3 = __float2half(v.w - __half2float(h3));
    dh[0] = __halves2half2(h0, h1); dh[1] = __halves2half2(h2, h3);
    dl[0] = __halves2half2(l0, l1); dl[1] = __halves2half2(l2, l3);
}

// ---------------- kernel 1: QKV projection via fp16x3 tensor-core mma ----------------
#define SROW 24            // halves per smem row (16 data + 8 pad) = 48B
#define PLANE (128*SROW)   // halves per plane (3072); 6144 B
#define NSTAGE 3
#define GEMM_SMEM (NSTAGE * 2 * 2 * PLANE * 2)   // 73728 bytes

#define CP_ASYNC16(dst, src) \
    asm volatile("cp.async.ca.shared.global [%0], [%1], 16;" :: "r"(dst), "l"(src))
#define CP_COMMIT() asm volatile("cp.async.commit_group;")
#define CP_WAIT1()  asm volatile("cp.async.wait_group 1;")
#define CP_WAIT0()  asm volatile("cp.async.wait_group 0;")

__device__ __forceinline__ void ldm4(unsigned int addr, unsigned int* r) {
    asm volatile("ldmatrix.sync.aligned.m8n8.x4.shared.b16 {%0,%1,%2,%3}, [%4];"
                 : "=r"(r[0]), "=r"(r[1]), "=r"(r[2]), "=r"(r[3]) : "r"(addr));
}
__device__ __forceinline__ void mma16816(float* c, const unsigned int* a, const unsigned int* b) {
    asm volatile("mma.sync.aligned.m16n8k16.row.col.f32.f16.f16.f32 "
                 "{%0,%1,%2,%3}, {%4,%5,%6,%7}, {%8,%9}, {%0,%1,%2,%3};"
                 : "+f"(c[0]), "+f"(c[1]), "+f"(c[2]), "+f"(c[3])
                 : "r"(a[0]), "r"(a[1]), "r"(a[2]), "r"(a[3]), "r"(b[0]), "r"(b[1]));
}

__global__ __launch_bounds__(256, 2) void gemm_mma(
    const float* __restrict__ bq, const float* __restrict__ bk, const float* __restrict__ bv) {
    extern __shared__ __align__(16) __half dsm[];
    // layout: A planes [stage][comp] = (s*2+c)*PLANE; B planes offset 6*PLANE
    int tid = threadIdx.x, lane = tid & 31, wid = tid >> 5;
    int warpM = wid >> 1, warpN = wid & 1;          // 4x2 warps -> 32x64 per warp
    int m0 = blockIdx.y * 128, n0 = blockIdx.x * 128;
    int w = n0 >> 9;
    const float* bias = (w == 0) ? bq : (w == 1) ? bk : bv;
    float* outp       = (w == 0) ? g_q : (w == 1) ? g_k : g_v;
    int i0 = n0 & 511;

    int grow = tid >> 1, gkh = tid & 1;
    const __half* pxh = &g_xh[(size_t)(m0 + grow) * 512 + gkh * 8];
    const __half* pxl = &g_xl[(size_t)(m0 + grow) * 512 + gkh * 8];
    const __half* pwh = &g_wh[(size_t)(w * 512 + i0 + grow) * 512 + gkh * 8];
    const __half* pwl = &g_wl[(size_t)(w * 512 + i0 + grow) * 512 + gkh * 8];
    unsigned int dst_off = (unsigned int)((grow * SROW + gkh * 8) * 2);  // bytes within plane
    unsigned int base = (unsigned int)__cvta_generic_to_shared(dsm);
    const unsigned int PB = PLANE * 2;          // plane bytes
    const unsigned int BOFF = 6 * PB;           // B region byte offset

    float acc[2][8][4];
    #pragma unroll
    for (int i = 0; i < 2; i++)
        #pragma unroll
        for (int j = 0; j < 8; j++)
            #pragma unroll
            for (int c = 0; c < 4; c++) acc[i][j][c] = 0.f;

    // prologue: stages 0,1 in flight (slabs 0,1)
    #pragma unroll
    for (int s = 0; s < 2; s++) {
        unsigned int sa = base + (s*2)*PB + dst_off;
        unsigned int sb = base + BOFF + (s*2)*PB + dst_off;
        CP_ASYNC16(sa,      pxh + s * 16);
        CP_ASYNC16(sa + PB, pxl + s * 16);
        CP_ASYNC16(sb,      pwh + s * 16);
        CP_ASYNC16(sb + PB, pwl + s * 16);
        CP_COMMIT();
    }

    int aRow = warpM * 32 + (lane & 15), aK = (lane >> 4) * 8;
    int bRow = warpN * 64 + 8 * (lane >> 4) + (lane & 7), bK = ((lane >> 3) & 1) * 8;

    #pragma unroll 1
    for (int ks = 0; ks < 32; ks++) {
        int cur = ks % NSTAGE;
        if (ks < 31) { CP_WAIT1(); } else { CP_WAIT0(); }
        __syncthreads();                 // slab ks resident; everyone done with iter ks-1

        // issue slab ks+2 into stage (ks+2)%3 (last read at iter ks-1 -> safe after sync)
        if (ks + 2 < 32) {
            int st = (ks + 2) % NSTAGE;
            unsigned int sa = base + (st*2)*PB + dst_off;
            unsigned int sb = base + BOFF + (st*2)*PB + dst_off;
            CP_ASYNC16(sa,      pxh + (ks + 2) * 16);
            CP_ASYNC16(sa + PB, pxl + (ks + 2) * 16);
            CP_ASYNC16(sb,      pwh + (ks + 2) * 16);
            CP_ASYNC16(sb + PB, pwl + (ks + 2) * 16);
            CP_COMMIT();
        }

        unsigned int afr[2][2][4];
        #pragma unroll
        for (int comp = 0; comp < 2; comp++)
            #pragma unroll
            for (int mt = 0; mt < 2; mt++) {
                unsigned int ad = base + (cur*2 + comp)*PB +
                    (unsigned int)(((aRow + mt * 16) * SROW + aK) * 2);
                ldm4(ad, afr[comp][mt]);
            }
        #pragma unroll
        for (int np = 0; np < 4; np++) {
            unsigned int bfr[2][4];
            #pragma unroll
            for (int comp = 0; comp < 2; comp++) {
                unsigned int bd = base + BOFF + (cur*2 + comp)*PB +
                    (unsigned int)(((bRow + np * 16) * SROW + bK) * 2);
                ldm4(bd, bfr[comp]);
            }
            #pragma unroll
            for (int mt = 0; mt < 2; mt++) {
                #pragma unroll
                for (int half = 0; half < 2; half++) {
                    int nt = np * 2 + half;
                    unsigned int bh_[2] = {bfr[0][half*2], bfr[0][half*2+1]};
                    unsigned int bl_[2] = {bfr[1][half*2], bfr[1][half*2+1]};
                    mma16816(acc[mt][nt], afr[0][mt], bh_);   // hi*hi
                    mma16816(acc[mt][nt], afr[0][mt], bl_);   // hi*lo
                    mma16816(acc[mt][nt], afr[1][mt], bh_);   // lo*hi
                }
            }
        }
    }

    // epilogue
    #pragma unroll
    for (int mt = 0; mt < 2; mt++) {
        int mr = m0 + warpM * 32 + mt * 16 + (lane >> 2);
        #pragma unroll
        for (int nt = 0; nt < 8; nt++) {
            int col = warpN * 64 + nt * 8 + 2 * (lane & 3);
            int i1 = i0 + col, i2 = i1 + 1;
            #pragma unroll
            for (int rh = 0; rh < 2; rh++) {
                int m = mr + rh * 8;
                int bh_ = (m >> 11) * HH;
                int l = m & 2047;
                float c0 = acc[mt][nt][rh*2], c1 = acc[mt][nt][rh*2+1];
                outp[((((size_t)(bh_ + (i1 >> 6))) << 11) + l) * 64 + (i1 & 63)] = c0 + bias[i1];
                outp[((((size_t)(bh_ + (i2 >> 6))) << 11) + l) * 64 + (i2 & 63)] = c1 + bias[i2];
            }
        }
    }
}

// ---------------- kernel 2: sampled scores -> M ----------------
__global__ void k_sampleM() {
    __shared__ float qsh[4][64];
    int w = threadIdx.x >> 5, lane = threadIdx.x & 31;
    int row = blockIdx.x * 4 + w;
    int bh = row >> 11, l = row & 2047;
    const float* qrow = g_q + ((size_t)row << 6);
    qsh[w][lane] = qrow[lane];
    qsh[w][lane + 32] = qrow[lane + 32];
    __syncwarp();
    const float4* q4 = (const float4*)qsh[w];

    float d0;
    {
        int idx = g_idx[l * SK + lane];
        const float4* kr = (const float4*)(g_k + ((((size_t)bh << 11) + idx) << 6));
        float s = 0.f;
        #pragma unroll
        for (int i = 0; i < 16; i++) {
            float4 a = q4[i], b = kr[i];
            s += a.x*b.x + a.y*b.y + a.z*b.z + a.w*b.w;
        }
        d0 = s;
    }
    float d1 = -INFINITY, s1 = 0.f;
    if (lane < SK - 32) {
        int idx = g_idx[l * SK + 32 + lane];
        const float4* kr = (const float4*)(g_k + ((((size_t)bh << 11) + idx) << 6));
        float s = 0.f;
        #pragma unroll
        for (int i = 0; i < 16; i++) {
            float4 a = q4[i], b = kr[i];
            s += a.x*b.x + a.y*b.y + a.z*b.z + a.w*b.w;
        }
        d1 = s; s1 = s;
    }
    float mx = fmaxf(d0, d1);
    float sm = d0 + s1;
    #pragma unroll
    for (int o = 16; o; o >>= 1) {
        mx = fmaxf(mx, __shfl_xor_sync(0xffffffffu, mx, o));
        sm += __shfl_xor_sync(0xffffffffu, sm, o);
    }
    if (lane == 0) g_M[row] = mx - sm * (1.0f / LL);
}

// ---------------- kernel 3: exact top-40 via radix select ----------------
__global__ void k_topk() {
    __shared__ unsigned int uvals[LL];
    __shared__ int hist[256];
    __shared__ int suf[256];
    __shared__ unsigned int s_prefix;
    __shared__ int s_want, s_slot;
    int bh = blockIdx.x, t = threadIdx.x;
    for (int j = t; j < LL; j += 256) {
        unsigned int b = __float_as_uint(g_M[bh * LL + j]);
        uvals[j] = (b & 0x80000000u) ? ~b : (b | 0x80000000u);
        g_rank[bh * LL + j] = -1;
    }
    if (t == 0) { s_want = UU; s_prefix = 0u; s_slot = 0; }
    __syncthreads();

    #pragma unroll
    for (int level = 0; level < 4; level++) {
        int shift = 24 - level * 8;
        unsigned int mask = (level == 0) ? 0u : (0xFFFFFFFFu << (32 - 8 * level));
        hist[t] = 0;
        __syncthreads();
        unsigned int pref = s_prefix;
        int want = s_want;
        for (int j = t; j < LL; j += 256) {
            unsigned int u = uvals[j];
            if ((u & mask) == pref)
                atomicAdd(&hist[(u >> shift) & 0xFF], 1);
        }
        __syncthreads();
        suf[t] = hist[t];
        __syncthreads();
        #pragma unroll
        for (int o = 1; o < 256; o <<= 1) {
            int v = (t + o < 256) ? suf[t + o] : 0;
            __syncthreads();
            suf[t] += v;
            __syncthreads();
        }
        int above = (t < 255) ? suf[t + 1] : 0;
        if (suf[t] >= want && above < want) {
            s_prefix = pref | ((unsigned int)t << shift);
            s_want = want - above;
        }
        __syncthreads();
    }

    unsigned int T = s_prefix;
    int r = s_want;
    for (int j = t; j < LL; j += 256) {
        unsigned int u = uvals[j];
        bool sel = false;
        if (u > T) sel = true;
        else if (u == T) {
            int rank_eq = 0;
            for (int j2 = 0; j2 < j; j2++) if (uvals[j2] == T) rank_eq++;
            sel = (rank_eq < r);
        }
        if (sel) {
            int slot = atomicAdd(&s_slot, 1);
            g_Mtop[bh * UU + slot] = j;
            g_rank[bh * LL + j] = slot;
        }
    }
}

// ---------------- kernel 4: scores = scale * Qtop @ K^T ----------------
#define KT 64
__global__ void k_scores() {
    __shared__ float qtop[UU * DK];
    __shared__ float kt[KT * 65];
    int bh = blockIdx.y, l0 = blockIdx.x * KT, t = threadIdx.x;
    for (int j = t; j < UU * DK; j += 256) {
        int u = j >> 6, d = j & 63;
        int rl = g_Mtop[bh * UU + u];
        qtop[j] = g_q[((((size_t)bh << 11) + rl) << 6) + d];
    }
    for (int j = t; j < KT * DK; j += 256) {
        int li = j >> 6, d = j & 63;
        kt[li * 65 + d] = g_k[((((size_t)bh << 11) + l0 + li) << 6) + d];
    }
    __syncthreads();
    int lsub = t & 63, ug = t >> 6;
    float accv[10];
    #pragma unroll
    for (int g = 0; g < 10; g++) accv[g] = 0.f;
    for (int d = 0; d < 64; d++) {
        float kv = kt[lsub * 65 + d];
        #pragma unroll
        for (int g = 0; g < 10; g++)
            accv[g] += qtop[(ug + 4 * g) * 64 + d] * kv;
    }
    #pragma unroll
    for (int g = 0; g < 10; g++) {
        int u = ug + 4 * g;
        g_scores[((size_t)(bh * UU + u) << 11) + l0 + lsub] = accv[g] * 0.125f;
    }
}

// ---------------- kernel 5: softmax stats ----------------
__global__ void k_stats() {
    __shared__ float red[256];
    int r = blockIdx.x, t = threadIdx.x;
    const float* s = g_scores + ((size_t)r << 11);
    float mx = -INFINITY;
    for (int j = t; j < LL; j += 256) mx = fmaxf(mx, s[j]);
    red[t] = mx; __syncthreads();
    for (int o = 128; o; o >>= 1) { if (t < o) red[t] = fmaxf(red[t], red[t + o]); __syncthreads(); }
    mx = red[0]; __syncthreads();
    float sm = 0.f;
    for (int j = t; j < LL; j += 256) sm += expf(s[j] - mx);
    red[t] = sm; __syncthreads();
    for (int o = 128; o; o >>= 1) { if (t < o) red[t] += red[t + o]; __syncthreads(); }
    if (t == 0) { g_mx[r] = mx; g_inv[r] = 1.0f / red[0]; }
}

// ---------------- cumsum (context) ----------------
__global__ void k_csum_part() {
    __shared__ float red[256];
    int blk = blockIdx.x;
    int bh = blk >> 4, c = blk & 15;
    int t = threadIdx.x, d = t & 63, p = t >> 6;
    const float* vb = g_v + ((((size_t)bh << 11) + c * CH) << 6);
    float s = 0.f;
    for (int i = 0; i < 32; i++) s += vb[(p * 32 + i) * 64 + d];
    red[t] = s; __syncthreads();
    if (t < 64)
        g_part[blk * 64 + t] = red[t] + red[t + 64] + red[t + 128] + red[t + 192];
}

__global__ void k_csum_off() {
    int bh = blockIdx.x, d = threadIdx.x;
    float run = 0.f;
    for (int c = 0; c < NCH; c++) {
        g_offs[(bh * NCH + c) * 64 + d] = run;
        run += g_part[(bh * NCH + c) * 64 + d];
    }
}

__global__ void k_csum_scan(float* __restrict__ ctx) {
    __shared__ float vsh[CH * 64];
    int blk = blockIdx.x;
    int bh = blk >> 4, c = blk & 15;
    int t = threadIdx.x;
    const float4* vb = (const float4*)(g_v + ((((size_t)bh << 11) + c * CH) << 6));
    float4* vs4 = (float4*)vsh;
    for (int j = t; j < CH * 16; j += 256) vs4[j] = vb[j];
    __syncthreads();
    if (t < 64) {
        float run = g_offs[(bh * NCH + c) * 64 + t];
        for (int i = 0; i < CH; i++) { run += vsh[i * 64 + t]; vsh[i * 64 + t] = run; }
    }
    __syncthreads();
    float4* ob = (float4*)(ctx + ((((size_t)bh << 11) + c * CH) << 6));
    for (int j = t; j < CH * 16; j += 256) ob[j] = vs4[j];
}

// ---------------- kernel 7: upd partials = attn @ V ----------------
__global__ void k_upd() {
    __shared__ float vsh[64 * 64];
    __shared__ float ash[UU * 64];
    __shared__ float smx[UU], sinv[UU];
    int bh = blockIdx.y, ls = blockIdx.x;
    int t = threadIdx.x;
    if (t < UU) { smx[t] = g_mx[bh * UU + t]; sinv[t] = g_inv[bh * UU + t]; }

    int lane2 = (t & 31) * 2, ug = t >> 5;
    float acc[5][2];
    #pragma unroll
    for (int uu = 0; uu < 5; uu++) { acc[uu][0] = 0.f; acc[uu][1] = 0.f; }

    for (int tile = 0; tile < 4; tile++) {
        int l0 = ls * 256 + tile * 64;
        __syncthreads();
        const float4* vb = (const float4*)(g_v + ((((size_t)bh << 11) + l0) << 6));
        float4* vs4 = (float4*)vsh;
        for (int j = t; j < 64 * 16; j += 256) vs4[j] = vb[j];
        for (int j = t; j < UU * 64; j += 256) {
            int u = j >> 6, li = j & 63;
            ash[j] = expf(g_scores[((size_t)(bh * UU + u) << 11) + l0 + li] - smx[u]) * sinv[u];
        }
        __syncthreads();
        for (int li = 0; li < 64; li++) {
            float v0 = vsh[li * 64 + lane2], v1 = vsh[li * 64 + lane2 + 1];
            #pragma unroll
            for (int uu = 0; uu < 5; uu++) {
                float a = ash[(ug * 5 + uu) * 64 + li];
                acc[uu][0] += a * v0;
                acc[uu][1] += a * v1;
            }
        }
    }
    #pragma unroll
    for (int uu = 0; uu < 5; uu++) {
        int r = bh * UU + ug * 5 + uu;
        g_updp[((size_t)ls * BH * UU + r) * 64 + lane2]     = acc[uu][0];
        g_updp[((size_t)ls * BH * UU + r) * 64 + lane2 + 1] = acc[uu][1];
    }
}

// ---------------- kernel 8: reduce upd partials + scatter into context ----------------
__global__ void k_scatter(float* __restrict__ ctx) {
    int r = blockIdx.x, d = threadIdx.x;
    int bh = r / UU;
    int l = g_Mtop[r];
    float s = 0.f;
    #pragma unroll
    for (int p = 0; p < 8; p++) s += g_updp[((size_t)p * BH * UU + r) * 64 + d];
    ctx[((((size_t)bh << 11) + l) << 6) + d] = s;
}

// ---------------- kernel 9: attns output ----------------
__global__ void k_attns(float* __restrict__ attns) {
    int row = blockIdx.x;
    int bh = row >> 11;
    int r = g_rank[row];
    float* out = attns + ((size_t)row << 11);
    int t = threadIdx.x;
    if (r < 0) {
        float4 c = make_float4(1.0f / LL, 1.0f / LL, 1.0f / LL, 1.0f / LL);
        float4* o4 = (float4*)out;
        o4[t] = c;
        o4[t + 256] = c;
    } else {
        float mx = g_mx[bh * UU + r], inv = g_inv[bh * UU + r];
        const float* s = g_scores + ((size_t)(bh * UU + r) << 11);
        #pragma unroll
        for (int j = 0; j < 2; j++) {
            int base = (t + j * 256) * 4;
            float4 sv = *(const float4*)(s + base);
            float4 ov;
            ov.x = expf(sv.x - mx) * inv;
            ov.y = expf(sv.y - mx) * inv;
            ov.z = expf(sv.z - mx) * inv;
            ov.w = expf(sv.w - mx) * inv;
            *(float4*)(out + base) = ov;
        }
    }
}

// ---------------- launch ----------------
extern "C" void kernel_launch(void* const* d_in, const int* in_sizes, int n_in,
                              void* d_out, int out_size) {
    const float* x  = (const float*)d_in[0];
    const float* Wq = (const float*)d_in[1];
    const float* bq = (const float*)d_in[2];
    const float* Wk = (const float*)d_in[3];
    const float* bk = (const float*)d_in[4];
    const float* Wv = (const float*)d_in[5];
    const float* bv = (const float*)d_in[6];
    const unsigned int* idxraw = (const unsigned int*)d_in[7];

    float* ctx   = (float*)d_out;
    float* attns = ctx + (size_t)BB * LL * DD;

    static int smem_set = 0;
    if (!smem_set) {
        cudaFuncSetAttribute(gemm_mma, cudaFuncAttributeMaxDynamicSharedMemorySize, GEMM_SMEM);
        smem_set = 1;
    }

    k_idx<<<16, 512>>>(idxraw, LL * SK);
    k_cvt<<<(BB*LL*DD/4 + 3*DD*DD/4 + 255)/256, 256>>>(x, Wq, Wk, Wv);
    gemm_mma<<<dim3(12, 32), 256, GEMM_SMEM>>>(bq, bk, bv);
    k_sampleM<<<NROWS / 4, 128>>>();            // profiled slot next round
    k_topk<<<BH, 256>>>();
    k_scores<<<dim3(LL / KT, BH), 256>>>();
    k_stats<<<BH * UU, 256>>>();
    k_csum_part<<<BH * NCH, 256>>>();
    k_csum_off<<<BH, 64>>>();
    k_csum_scan<<<BH * NCH, 256>>>(ctx);
    k_upd<<<dim3(8, BH), 256>>>();
    k_scatter<<<BH * UU, 64>>>(ctx);
    k_attns<<<NROWS, 256>>>(attns);
}

// round 9
// speedup vs baseline: 1.9805x; 1.2408x over previous
#include <cuda_runtime.h>
#include <cuda_fp16.h>
#include <math.h>

#define BB 2
#define LL 2048
#define DD 512
#define HH 8
#define DK 64
#define SK 40
#define UU 40
#define BH 16            // BB*HH
#define NROWS 32768      // BH*LL
#define NCH 16           // cumsum chunks per (b,h)
#define CH 128           // L per chunk

// ---------------- scratch (device globals; no allocation) ----------------
__device__ float g_q[BB*HH*LL*DK];
__device__ float g_k[BB*HH*LL*DK];
__device__ float g_v[BB*HH*LL*DK];
__device__ float g_scores[BH*UU*LL];
__device__ float g_M[NROWS];
__device__ int   g_Mtop[BH*UU];
__device__ int   g_rank[NROWS];
__device__ float g_mx[BH*UU];
__device__ float g_inv[BH*UU];
__device__ float g_part[BH*NCH*DK];
__device__ float g_offs[BH*NCH*DK];
__device__ float g_updp[8*BH*UU*DK];
__device__ int   g_idx[LL*SK];
// fp16x3 split operands (16B-aligned for float4 access)
__device__ __align__(16) __half g_xh[BB*LL*DD];
__device__ __align__(16) __half g_xl[BB*LL*DD];
__device__ __align__(16) __half g_wh[3*DD*DD];
__device__ __align__(16) __half g_wl[3*DD*DD];

// ---------------- kernel 0: normalize index_sample (int32 vs int64), 16 blocks ----------------
__global__ void k_idx(const unsigned int* __restrict__ raw, int nelem) {
    __shared__ int s_flag;
    int per = nelem / gridDim.x;
    int wbase = blockIdx.x * per;
    if (threadIdx.x == 0) s_flag = 0;
    __syncthreads();
    int local = 0;
    for (int j = threadIdx.x * 2 + 1; j < per; j += blockDim.x * 2)
        if (raw[wbase + j] != 0u) local = 1;
    if (local) atomicOr(&s_flag, 1);
    __syncthreads();
    int is32 = s_flag;
    int ebase = blockIdx.x * per;
    for (int e = ebase + threadIdx.x; e < ebase + per; e += blockDim.x)
        g_idx[e] = is32 ? (int)raw[e] : (int)raw[2 * e];
}

// ---------------- fused fp16 hi/lo split converter (x then W) ----------------
__global__ void k_cvt(const float* __restrict__ x, const float* __restrict__ Wq,
                      const float* __restrict__ Wk, const float* __restrict__ Wv) {
    const int NX = BB*LL*DD/4;
    const int PW = DD*DD/4;
    int i4 = blockIdx.x * blockDim.x + threadIdx.x;
    const float* src;
    __half2 *dh, *dl;
    int j4;
    if (i4 < NX) {
        src = x; j4 = i4;
        dh = (__half2*)g_xh + i4*2; dl = (__half2*)g_xl + i4*2;
    } else {
        int k = i4 - NX;
        if (k >= 3*PW) return;
        src = (k < PW) ? Wq : (k < 2*PW) ? Wk : Wv;
        j4  = (k < PW) ? k  : (k < 2*PW) ? k - PW : k - 2*PW;
        dh = (__half2*)g_wh + k*2; dl = (__half2*)g_wl + k*2;
    }
    float4 v = ((const float4*)src)[j4];
    __half h0 = __float2half(v.x), h1 = __float2half(v.y);
    __half h2 = __float2half(v.z), h3 = __float2half(v.w);
    __half l0 = __float2half(v.x - __half2float(h0));
    __half l1 = __float2half(v.y - __half2float(h1));
    __half l2 = __float2half(v.z - __half2float(h2));
    __half l3 = __float2half(v.w - __half2float(h3));
    dh[0] = __halves2half2(h0, h1); dh[1] = __halves2half2(h2, h3);
    dl[0] = __halves2half2(l0, l1); dl[1] = __halves2half2(l2, l3);
}

// ---------------- kernel 1: QKV projection via fp16x3 tensor-core mma ----------------
#define SROW 24            // halves per smem row (16 data + 8 pad) = 48B
#define PLANE (128*SROW)   // halves per plane (3072); 6144 B
#define NSTAGE 3
#define GEMM_SMEM (NSTAGE * 2 * 2 * PLANE * 2)   // 73728 bytes

#define CP_ASYNC16(dst, src) \
    asm volatile("cp.async.ca.shared.global [%0], [%1], 16;" :: "r"(dst), "l"(src))
#define CP_COMMIT() asm volatile("cp.async.commit_group;")
#define CP_WAIT1()  asm volatile("cp.async.wait_group 1;")
#define CP_WAIT0()  asm volatile("cp.async.wait_group 0;")

__device__ __forceinline__ void ldm4(unsigned int addr, unsigned int* r) {
    asm volatile("ldmatrix.sync.aligned.m8n8.x4.shared.b16 {%0,%1,%2,%3}, [%4];"
                 : "=r"(r[0]), "=r"(r[1]), "=r"(r[2]), "=r"(r[3]) : "r"(addr));
}
__device__ __forceinline__ void mma16816(float* c, const unsigned int* a, const unsigned int* b) {
    asm volatile("mma.sync.aligned.m16n8k16.row.col.f32.f16.f16.f32 "
                 "{%0,%1,%2,%3}, {%4,%5,%6,%7}, {%8,%9}, {%0,%1,%2,%3};"
                 : "+f"(c[0]), "+f"(c[1]), "+f"(c[2]), "+f"(c[3])
                 : "r"(a[0]), "r"(a[1]), "r"(a[2]), "r"(a[3]), "r"(b[0]), "r"(b[1]));
}

__global__ __launch_bounds__(256, 2) void gemm_mma(
    const float* __restrict__ bq, const float* __restrict__ bk, const float* __restrict__ bv) {
    extern __shared__ __align__(16) __half dsm[];
    int tid = threadIdx.x, lane = tid & 31, wid = tid >> 5;
    int warpM = wid >> 1, warpN = wid & 1;
    int m0 = blockIdx.y * 128, n0 = blockIdx.x * 128;
    int w = n0 >> 9;
    const float* bias = (w == 0) ? bq : (w == 1) ? bk : bv;
    float* outp       = (w == 0) ? g_q : (w == 1) ? g_k : g_v;
    int i0 = n0 & 511;

    int grow = tid >> 1, gkh = tid & 1;
    const __half* pxh = &g_xh[(size_t)(m0 + grow) * 512 + gkh * 8];
    const __half* pxl = &g_xl[(size_t)(m0 + grow) * 512 + gkh * 8];
    const __half* pwh = &g_wh[(size_t)(w * 512 + i0 + grow) * 512 + gkh * 8];
    const __half* pwl = &g_wl[(size_t)(w * 512 + i0 + grow) * 512 + gkh * 8];
    unsigned int dst_off = (unsigned int)((grow * SROW + gkh * 8) * 2);
    unsigned int base = (unsigned int)__cvta_generic_to_shared(dsm);
    const unsigned int PB = PLANE * 2;
    const unsigned int BOFF = 6 * PB;

    float acc[2][8][4];
    #pragma unroll
    for (int i = 0; i < 2; i++)
        #pragma unroll
        for (int j = 0; j < 8; j++)
            #pragma unroll
            for (int c = 0; c < 4; c++) acc[i][j][c] = 0.f;

    #pragma unroll
    for (int s = 0; s < 2; s++) {
        unsigned int sa = base + (s*2)*PB + dst_off;
        unsigned int sb = base + BOFF + (s*2)*PB + dst_off;
        CP_ASYNC16(sa,      pxh + s * 16);
        CP_ASYNC16(sa + PB, pxl + s * 16);
        CP_ASYNC16(sb,      pwh + s * 16);
        CP_ASYNC16(sb + PB, pwl + s * 16);
        CP_COMMIT();
    }

    int aRow = warpM * 32 + (lane & 15), aK = (lane >> 4) * 8;
    int bRow = warpN * 64 + 8 * (lane >> 4) + (lane & 7), bK = ((lane >> 3) & 1) * 8;

    #pragma unroll 1
    for (int ks = 0; ks < 32; ks++) {
        int cur = ks % NSTAGE;
        if (ks < 31) { CP_WAIT1(); } else { CP_WAIT0(); }
        __syncthreads();

        if (ks + 2 < 32) {
            int st = (ks + 2) % NSTAGE;
            unsigned int sa = base + (st*2)*PB + dst_off;
            unsigned int sb = base + BOFF + (st*2)*PB + dst_off;
            CP_ASYNC16(sa,      pxh + (ks + 2) * 16);
            CP_ASYNC16(sa + PB, pxl + (ks + 2) * 16);
            CP_ASYNC16(sb,      pwh + (ks + 2) * 16);
            CP_ASYNC16(sb + PB, pwl + (ks + 2) * 16);
            CP_COMMIT();
        }

        unsigned int afr[2][2][4];
        #pragma unroll
        for (int comp = 0; comp < 2; comp++)
            #pragma unroll
            for (int mt = 0; mt < 2; mt++) {
                unsigned int ad = base + (cur*2 + comp)*PB +
                    (unsigned int)(((aRow + mt * 16) * SROW + aK) * 2);
                ldm4(ad, afr[comp][mt]);
            }
        #pragma unroll
        for (int np = 0; np < 4; np++) {
            unsigned int bfr[2][4];
            #pragma unroll
            for (int comp = 0; comp < 2; comp++) {
                unsigned int bd = base + BOFF + (cur*2 + comp)*PB +
                    (unsigned int)(((bRow + np * 16) * SROW + bK) * 2);
                ldm4(bd, bfr[comp]);
            }
            #pragma unroll
            for (int mt = 0; mt < 2; mt++) {
                #pragma unroll
                for (int half = 0; half < 2; half++) {
                    int nt = np * 2 + half;
                    unsigned int bh_[2] = {bfr[0][half*2], bfr[0][half*2+1]};
                    unsigned int bl_[2] = {bfr[1][half*2], bfr[1][half*2+1]};
                    mma16816(acc[mt][nt], afr[0][mt], bh_);
                    mma16816(acc[mt][nt], afr[0][mt], bl_);
                    mma16816(acc[mt][nt], afr[1][mt], bh_);
                }
            }
        }
    }

    #pragma unroll
    for (int mt = 0; mt < 2; mt++) {
        int mr = m0 + warpM * 32 + mt * 16 + (lane >> 2);
        #pragma unroll
        for (int nt = 0; nt < 8; nt++) {
            int col = warpN * 64 + nt * 8 + 2 * (lane & 3);
            int i1 = i0 + col, i2 = i1 + 1;
            #pragma unroll
            for (int rh = 0; rh < 2; rh++) {
                int m = mr + rh * 8;
                int bh_ = (m >> 11) * HH;
                int l = m & 2047;
                float c0 = acc[mt][nt][rh*2], c1 = acc[mt][nt][rh*2+1];
                outp[((((size_t)(bh_ + (i1 >> 6))) << 11) + l) * 64 + (i1 & 63)] = c0 + bias[i1];
                outp[((((size_t)(bh_ + (i2 >> 6))) << 11) + l) * 64 + (i2 & 63)] = c1 + bias[i2];
            }
        }
    }
}

// ---------------- kernel 2: sampled scores -> M (coalesced gather) ----------------
// One warp per q-row. 16 lanes cover one sampled K-row (float4 each = full 256B),
// two samples per iteration. Butterfly-reduce within 16-lane groups.
__global__ __launch_bounds__(256) void k_sampleM() {
    __shared__ int sidx[8][SK];
    int wid = threadIdx.x >> 5, lane = threadIdx.x & 31;
    int row = blockIdx.x * 8 + wid;              // bh*L + l
    int bh = row >> 11, l = row & 2047;
    // q fragment: this lane's 4 d-values
    float4 qf = ((const float4*)(g_q + ((size_t)row << 6)))[lane & 15];
    sidx[wid][lane] = g_idx[l * SK + lane];                       // slots 0..31
    if (lane < SK - 32) sidx[wid][lane + 32] = g_idx[l * SK + lane + 32];  // slots 32..39
    __syncwarp();
    int half = lane >> 4;
    float mx = -INFINITY, sm = 0.f;
    const float* kb = g_k + ((size_t)bh << 17);  // bh * L * DK
    #pragma unroll
    for (int it = 0; it < SK / 2; it++) {
        int idx = sidx[wid][2 * it + half];
        float4 kf = ((const float4*)(kb + ((size_t)idx << 6)))[lane & 15];
        float p = qf.x*kf.x + qf.y*kf.y + qf.z*kf.z + qf.w*kf.w;
        p += __shfl_xor_sync(0xffffffffu, p, 1);
        p += __shfl_xor_sync(0xffffffffu, p, 2);
        p += __shfl_xor_sync(0xffffffffu, p, 4);
        p += __shfl_xor_sync(0xffffffffu, p, 8);
        mx = fmaxf(mx, p);
        sm += p;
    }
    mx = fmaxf(mx, __shfl_xor_sync(0xffffffffu, mx, 16));
    sm += __shfl_xor_sync(0xffffffffu, sm, 16);
    if (lane == 0) g_M[row] = mx - sm * (1.0f / LL);
}

// ---------------- kernel 3: exact top-40 via radix select ----------------
__global__ void k_topk() {
    __shared__ unsigned int uvals[LL];
    __shared__ int hist[256];
    __shared__ int suf[256];
    __shared__ unsigned int s_prefix;
    __shared__ int s_want, s_slot;
    int bh = blockIdx.x, t = threadIdx.x;
    for (int j = t; j < LL; j += 256) {
        unsigned int b = __float_as_uint(g_M[bh * LL + j]);
        uvals[j] = (b & 0x80000000u) ? ~b : (b | 0x80000000u);
        g_rank[bh * LL + j] = -1;
    }
    if (t == 0) { s_want = UU; s_prefix = 0u; s_slot = 0; }
    __syncthreads();

    #pragma unroll
    for (int level = 0; level < 4; level++) {
        int shift = 24 - level * 8;
        unsigned int mask = (level == 0) ? 0u : (0xFFFFFFFFu << (32 - 8 * level));
        hist[t] = 0;
        __syncthreads();
        unsigned int pref = s_prefix;
        int want = s_want;
        for (int j = t; j < LL; j += 256) {
            unsigned int u = uvals[j];
            if ((u & mask) == pref)
                atomicAdd(&hist[(u >> shift) & 0xFF], 1);
        }
        __syncthreads();
        suf[t] = hist[t];
        __syncthreads();
        #pragma unroll
        for (int o = 1; o < 256; o <<= 1) {
            int v = (t + o < 256) ? suf[t + o] : 0;
            __syncthreads();
            suf[t] += v;
            __syncthreads();
        }
        int above = (t < 255) ? suf[t + 1] : 0;
        if (suf[t] >= want && above < want) {
            s_prefix = pref | ((unsigned int)t << shift);
            s_want = want - above;
        }
        __syncthreads();
    }

    unsigned int T = s_prefix;
    int r = s_want;
    for (int j = t; j < LL; j += 256) {
        unsigned int u = uvals[j];
        bool sel = false;
        if (u > T) sel = true;
        else if (u == T) {
            int rank_eq = 0;
            for (int j2 = 0; j2 < j; j2++) if (uvals[j2] == T) rank_eq++;
            sel = (rank_eq < r);
        }
        if (sel) {
            int slot = atomicAdd(&s_slot, 1);
            g_Mtop[bh * UU + slot] = j;
            g_rank[bh * LL + j] = slot;
        }
    }
}

// ---------------- kernel 4: scores = scale * Qtop @ K^T ----------------
#define KT 64
__global__ void k_scores() {
    __shared__ float qtop[UU * DK];
    __shared__ float kt[KT * 65];
    int bh = blockIdx.y, l0 = blockIdx.x * KT, t = threadIdx.x;
    for (int j = t; j < UU * DK; j += 256) {
        int u = j >> 6, d = j & 63;
        int rl = g_Mtop[bh * UU + u];
        qtop[j] = g_q[((((size_t)bh << 11) + rl) << 6) + d];
    }
    for (int j = t; j < KT * DK; j += 256) {
        int li = j >> 6, d = j & 63;
        kt[li * 65 + d] = g_k[((((size_t)bh << 11) + l0 + li) << 6) + d];
    }
    __syncthreads();
    int lsub = t & 63, ug = t >> 6;
    float accv[10];
    #pragma unroll
    for (int g = 0; g < 10; g++) accv[g] = 0.f;
    for (int d = 0; d < 64; d++) {
        float kv = kt[lsub * 65 + d];
        #pragma unroll
        for (int g = 0; g < 10; g++)
            accv[g] += qtop[(ug + 4 * g) * 64 + d] * kv;
    }
    #pragma unroll
    for (int g = 0; g < 10; g++) {
        int u = ug + 4 * g;
        g_scores[((size_t)(bh * UU + u) << 11) + l0 + lsub] = accv[g] * 0.125f;
    }
}

// ---------------- kernel 5: softmax stats ----------------
__global__ void k_stats() {
    __shared__ float red[256];
    int r = blockIdx.x, t = threadIdx.x;
    const float* s = g_scores + ((size_t)r << 11);
    float mx = -INFINITY;
    for (int j = t; j < LL; j += 256) mx = fmaxf(mx, s[j]);
    red[t] = mx; __syncthreads();
    for (int o = 128; o; o >>= 1) { if (t < o) red[t] = fmaxf(red[t], red[t + o]); __syncthreads(); }
    mx = red[0]; __syncthreads();
    float sm = 0.f;
    for (int j = t; j < LL; j += 256) sm += expf(s[j] - mx);
    red[t] = sm; __syncthreads();
    for (int o = 128; o; o >>= 1) { if (t < o) red[t] += red[t + o]; __syncthreads(); }
    if (t == 0) { g_mx[r] = mx; g_inv[r] = 1.0f / red[0]; }
}

// ---------------- cumsum (context) ----------------
__global__ void k_csum_part() {
    __shared__ float red[256];
    int blk = blockIdx.x;
    int bh = blk >> 4, c = blk & 15;
    int t = threadIdx.x, d = t & 63, p = t >> 6;
    const float* vb = g_v + ((((size_t)bh << 11) + c * CH) << 6);
    float s = 0.f;
    for (int i = 0; i < 32; i++) s += vb[(p * 32 + i) * 64 + d];
    red[t] = s; __syncthreads();
    if (t < 64)
        g_part[blk * 64 + t] = red[t] + red[t + 64] + red[t + 128] + red[t + 192];
}

__global__ void k_csum_off() {
    int bh = blockIdx.x, d = threadIdx.x;
    float run = 0.f;
    for (int c = 0; c < NCH; c++) {
        g_offs[(bh * NCH + c) * 64 + d] = run;
        run += g_part[(bh * NCH + c) * 64 + d];
    }
}

__global__ void k_csum_scan(float* __restrict__ ctx) {
    __shared__ float vsh[CH * 64];
    int blk = blockIdx.x;
    int bh = blk >> 4, c = blk & 15;
    int t = threadIdx.x;
    const float4* vb = (const float4*)(g_v + ((((size_t)bh << 11) + c * CH) << 6));
    float4* vs4 = (float4*)vsh;
    for (int j = t; j < CH * 16; j += 256) vs4[j] = vb[j];
    __syncthreads();
    if (t < 64) {
        float run = g_offs[(bh * NCH + c) * 64 + t];
        for (int i = 0; i < CH; i++) { run += vsh[i * 64 + t]; vsh[i * 64 + t] = run; }
    }
    __syncthreads();
    float4* ob = (float4*)(ctx + ((((size_t)bh << 11) + c * CH) << 6));
    for (int j = t; j < CH * 16; j += 256) ob[j] = vs4[j];
}

// ---------------- kernel 7: upd partials = attn @ V ----------------
__global__ void k_upd() {
    __shared__ float vsh[64 * 64];
    __shared__ float ash[UU * 64];
    __shared__ float smx[UU], sinv[UU];
    int bh = blockIdx.y, ls = blockIdx.x;
    int t = threadIdx.x;
    if (t < UU) { smx[t] = g_mx[bh * UU + t]; sinv[t] = g_inv[bh * UU + t]; }

    int lane2 = (t & 31) * 2, ug = t >> 5;
    float acc[5][2];
    #pragma unroll
    for (int uu = 0; uu < 5; uu++) { acc[uu][0] = 0.f; acc[uu][1] = 0.f; }

    for (int tile = 0; tile < 4; tile++) {
        int l0 = ls * 256 + tile * 64;
        __syncthreads();
        const float4* vb = (const float4*)(g_v + ((((size_t)bh << 11) + l0) << 6));
        float4* vs4 = (float4*)vsh;
        for (int j = t; j < 64 * 16; j += 256) vs4[j] = vb[j];
        for (int j = t; j < UU * 64; j += 256) {
            int u = j >> 6, li = j & 63;
            ash[j] = expf(g_scores[((size_t)(bh * UU + u) << 11) + l0 + li] - smx[u]) * sinv[u];
        }
        __syncthreads();
        for (int li = 0; li < 64; li++) {
            float v0 = vsh[li * 64 + lane2], v1 = vsh[li * 64 + lane2 + 1];
            #pragma unroll
            for (int uu = 0; uu < 5; uu++) {
                float a = ash[(ug * 5 + uu) * 64 + li];
                acc[uu][0] += a * v0;
                acc[uu][1] += a * v1;
            }
        }
    }
    #pragma unroll
    for (int uu = 0; uu < 5; uu++) {
        int r = bh * UU + ug * 5 + uu;
        g_updp[((size_t)ls * BH * UU + r) * 64 + lane2]     = acc[uu][0];
        g_updp[((size_t)ls * BH * UU + r) * 64 + lane2 + 1] = acc[uu][1];
    }
}

// ---------------- kernel 8: reduce upd partials + scatter into context ----------------
__global__ void k_scatter(float* __restrict__ ctx) {
    int r = blockIdx.x, d = threadIdx.x;
    int bh = r / UU;
    int l = g_Mtop[r];
    float s = 0.f;
    #pragma unroll
    for (int p = 0; p < 8; p++) s += g_updp[((size_t)p * BH * UU + r) * 64 + d];
    ctx[((((size_t)bh << 11) + l) << 6) + d] = s;
}

// ---------------- kernel 9: attns output ----------------
__global__ void k_attns(float* __restrict__ attns) {
    int row = blockIdx.x;
    int bh = row >> 11;
    int r = g_rank[row];
    float* out = attns + ((size_t)row << 11);
    int t = threadIdx.x;
    if (r < 0) {
        float4 c = make_float4(1.0f / LL, 1.0f / LL, 1.0f / LL, 1.0f / LL);
        float4* o4 = (float4*)out;
        o4[t] = c;
        o4[t + 256] = c;
    } else {
        float mx = g_mx[bh * UU + r], inv = g_inv[bh * UU + r];
        const float* s = g_scores + ((size_t)(bh * UU + r) << 11);
        #pragma unroll
        for (int j = 0; j < 2; j++) {
            int base = (t + j * 256) * 4;
            float4 sv = *(const float4*)(s + base);
            float4 ov;
            ov.x = expf(sv.x - mx) * inv;
            ov.y = expf(sv.y - mx) * inv;
            ov.z = expf(sv.z - mx) * inv;
            ov.w = expf(sv.w - mx) * inv;
            *(float4*)(out + base) = ov;
        }
    }
}

// ---------------- launch ----------------
extern "C" void kernel_launch(void* const* d_in, const int* in_sizes, int n_in,
                              void* d_out, int out_size) {
    const float* x  = (const float*)d_in[0];
    const float* Wq = (const float*)d_in[1];
    const float* bq = (const float*)d_in[2];
    const float* Wk = (const float*)d_in[3];
    const float* bk = (const float*)d_in[4];
    const float* Wv = (const float*)d_in[5];
    const float* bv = (const float*)d_in[6];
    const unsigned int* idxraw = (const unsigned int*)d_in[7];

    float* ctx   = (float*)d_out;
    float* attns = ctx + (size_t)BB * LL * DD;

    static int smem_set = 0;
    if (!smem_set) {
        cudaFuncSetAttribute(gemm_mma, cudaFuncAttributeMaxDynamicSharedMemorySize, GEMM_SMEM);
        smem_set = 1;
    }

    k_idx<<<16, 512>>>(idxraw, LL * SK);
    k_cvt<<<(BB*LL*DD/4 + 3*DD*DD/4 + 255)/256, 256>>>(x, Wq, Wk, Wv);
    gemm_mma<<<dim3(12, 32), 256, GEMM_SMEM>>>(bq, bk, bv);
    k_sampleM<<<NROWS / 8, 256>>>();            // profiled slot (4th launch)
    k_topk<<<BH, 256>>>();
    k_scores<<<dim3(LL / KT, BH), 256>>>();
    k_stats<<<BH * UU, 256>>>();
    k_csum_part<<<BH * NCH, 256>>>();
    k_csum_off<<<BH, 64>>>();
    k_csum_scan<<<BH * NCH, 256>>>(ctx);
    k_upd<<<dim3(8, BH), 256>>>();
    k_scatter<<<BH * UU, 64>>>(ctx);
    k_attns<<<NROWS, 256>>>(attns);
}